// round 3
// baseline (speedup 1.0000x reference)
#include <cuda_runtime.h>
#include <math.h>

// Problem constants (fixed by the dataset)
constexpr int NN = 50000;   // nodes
constexpr int EE = 800000;  // edges

// ---------------- scratch (static __device__ — no allocation) --------------
__device__ float g_dinv[NN];            // deg -> rsqrt(deg)
__device__ float g_xl  [NN * 64];       // x @ W1
__device__ float g_agg [NN * 64];       // aggregated layer-1 (pre-relu, pre-b1)
__device__ float g_l   [NN * 16];       // relu(h) @ W2, padded 10->16
__device__ float g_agg2[NN * 16];       // aggregated layer-2
__device__ int   g_eidx[2 * EE];        // normalized int32 [src | dst]
__device__ unsigned g_is32;             // 1 if edge_index is int32

// ---------------- edge-index dtype detect + normalize ----------------------
__global__ void k_flag_init() { g_is32 = 0u; }

// Scan the first 2E 32-bit words (safe under either dtype). For int64 input
// these are (lo,hi) pairs of the src row with hi==0 always; for int32 input
// odd words are random node ids -> some nonzero.
__global__ void k_detect(const unsigned* __restrict__ p, int e2) {
    int i = blockIdx.x * blockDim.x + threadIdx.x;
    if (i < e2 / 2) {
        if (p[2 * i + 1] != 0u) atomicOr(&g_is32, 1u);
    }
}

__global__ void k_convert(const void* __restrict__ p, int e2) {
    int i = blockIdx.x * blockDim.x + threadIdx.x;
    if (i >= e2) return;
    if (g_is32) g_eidx[i] = ((const int*)p)[i];
    else        g_eidx[i] = (int)((const long long*)p)[i];
}

// ---------------- degree / norm -------------------------------------------
__global__ void k_deg_init(int n) {
    int i = blockIdx.x * blockDim.x + threadIdx.x;
    if (i < n) g_dinv[i] = 1.0f;  // self-loop contributes 1
}

__global__ void k_deg_count(int e) {
    int i = blockIdx.x * blockDim.x + threadIdx.x;
    if (i < e) atomicAdd(&g_dinv[g_eidx[EE + i]], 1.0f);
}

__global__ void k_deg_rsqrt(int n) {
    int i = blockIdx.x * blockDim.x + threadIdx.x;
    if (i < n) g_dinv[i] = rsqrtf(g_dinv[i]);  // deg >= 1 always (self-loop)
}

// ---------------- GEMM1: xl = x @ W1  (n x 64) @ (64 x 64) ----------------
__global__ __launch_bounds__(256) void k_gemm1(const float* __restrict__ x,
                                               const float* __restrict__ W,
                                               int n) {
    __shared__ float As[64 * 65];  // x tile, padded rows (bank-conflict-free)
    __shared__ float Bs[64 * 64];  // W1
    const int tid = threadIdx.x;
    const int row0 = blockIdx.x * 64;

    for (int i = tid; i < 4096; i += 256) Bs[i] = W[i];
    for (int i = tid; i < 4096; i += 256) {
        int r = i >> 6, k = i & 63;
        int gr = row0 + r;
        As[r * 65 + k] = (gr < n) ? x[gr * 64 + k] : 0.0f;
    }
    __syncthreads();

    const int tx = tid & 15;  // output col group (4 cols)
    const int ty = tid >> 4;  // output row group (4 rows)

    float acc[4][4];
#pragma unroll
    for (int i = 0; i < 4; i++)
#pragma unroll
        for (int j = 0; j < 4; j++) acc[i][j] = 0.0f;

#pragma unroll
    for (int k = 0; k < 64; k++) {
        float4 b = *(const float4*)&Bs[k * 64 + tx * 4];
        float a[4];
#pragma unroll
        for (int i = 0; i < 4; i++) a[i] = As[(ty * 4 + i) * 65 + k];
#pragma unroll
        for (int i = 0; i < 4; i++) {
            acc[i][0] = fmaf(a[i], b.x, acc[i][0]);
            acc[i][1] = fmaf(a[i], b.y, acc[i][1]);
            acc[i][2] = fmaf(a[i], b.z, acc[i][2]);
            acc[i][3] = fmaf(a[i], b.w, acc[i][3]);
        }
    }

#pragma unroll
    for (int i = 0; i < 4; i++) {
        int r = row0 + ty * 4 + i;
        if (r < n) {
            float4 v = make_float4(acc[i][0], acc[i][1], acc[i][2], acc[i][3]);
            *(float4*)&g_xl[r * 64 + tx * 4] = v;
        }
    }
}

// ---------------- layer-1 aggregate ----------------------------------------
// init with self-loop contribution: agg[i] = xl[i] * dinv[i]^2
__global__ void k_agg1_init(int n) {
    int t = blockIdx.x * blockDim.x + threadIdx.x;
    if (t < n * 64) {
        int i = t >> 6;
        float d = g_dinv[i];
        g_agg[t] = g_xl[t] * d * d;
    }
}

// edge scatter: 16 threads / edge, each handles 4 contiguous cols.
// Loads stay vectorized (float4); reductions are scalar atomicAdd (REDG).
__global__ __launch_bounds__(256) void k_scatter1(int e) {
    int t = blockIdx.x * blockDim.x + threadIdx.x;
    int ei = t >> 4;
    if (ei >= e) return;
    int c4 = (t & 15) * 4;
    int s = g_eidx[ei];
    int d = g_eidx[EE + ei];
    float w = g_dinv[s] * g_dinv[d];
    float4 v = *(const float4*)&g_xl[s * 64 + c4];
    float* p = &g_agg[d * 64 + c4];
    atomicAdd(p + 0, v.x * w);
    atomicAdd(p + 1, v.y * w);
    atomicAdd(p + 2, v.z * w);
    atomicAdd(p + 3, v.w * w);
}

// ---------------- GEMM2 fused relu+b1: l = relu(agg + b1) @ W2 -------------
// block = 256 threads = 16 nodes x 16 cols (cols 10..15 padded with zero W)
__global__ __launch_bounds__(256) void k_gemm2(const float* __restrict__ b1,
                                               const float* __restrict__ W2,
                                               int n) {
    __shared__ float Hs[16 * 64];
    __shared__ float W2s[64 * 16];
    const int tid = threadIdx.x;
    const int node0 = blockIdx.x * 16;

    // stage W2 (64x10) padded to 64x16
    for (int i = tid; i < 64 * 16; i += 256) {
        int k = i >> 4, j = i & 15;
        W2s[i] = (j < 10) ? W2[k * 10 + j] : 0.0f;
    }
    // stage relu(agg + b1) rows
    for (int i = tid; i < 16 * 64; i += 256) {
        int g = i >> 6, k = i & 63;
        int r = node0 + g;
        float v = 0.0f;
        if (r < n) v = fmaxf(g_agg[r * 64 + k] + b1[k], 0.0f);
        Hs[i] = v;
    }
    __syncthreads();

    const int g = tid >> 4;  // node within block
    const int j = tid & 15;  // output col
    int r = node0 + g;
    if (r >= n) return;

    float acc = 0.0f;
#pragma unroll
    for (int k = 0; k < 64; k++) acc = fmaf(Hs[g * 64 + k], W2s[k * 16 + j], acc);
    g_l[r * 16 + j] = acc;
}

// ---------------- layer-2 aggregate ----------------------------------------
__global__ void k_agg2_init(int n) {
    int t = blockIdx.x * blockDim.x + threadIdx.x;
    if (t < n * 16) {
        int i = t >> 4;
        float d = g_dinv[i];
        g_agg2[t] = g_l[t] * d * d;
    }
}

// 4 threads / edge, each a float4 load + 4 scalar atomics over the 16-pad row
__global__ __launch_bounds__(256) void k_scatter2(int e) {
    int t = blockIdx.x * blockDim.x + threadIdx.x;
    int ei = t >> 2;
    if (ei >= e) return;
    int c4 = (t & 3) * 4;
    int s = g_eidx[ei];
    int d = g_eidx[EE + ei];
    float w = g_dinv[s] * g_dinv[d];
    float4 v = *(const float4*)&g_l[s * 16 + c4];
    float* p = &g_agg2[d * 16 + c4];
    atomicAdd(p + 0, v.x * w);
    atomicAdd(p + 1, v.y * w);
    atomicAdd(p + 2, v.z * w);
    atomicAdd(p + 3, v.w * w);
}

// ---------------- epilogue: +b2, log_softmax over 10 classes ----------------
__global__ void k_logsoftmax(const float* __restrict__ b2,
                             float* __restrict__ out, int n) {
    int i = blockIdx.x * blockDim.x + threadIdx.x;
    if (i >= n) return;
    float v[10];
    float m = -1e30f;
#pragma unroll
    for (int j = 0; j < 10; j++) {
        v[j] = g_agg2[i * 16 + j] + b2[j];
        m = fmaxf(m, v[j]);
    }
    float s = 0.0f;
#pragma unroll
    for (int j = 0; j < 10; j++) s += __expf(v[j] - m);
    float lse = m + __logf(s);
#pragma unroll
    for (int j = 0; j < 10; j++) out[i * 10 + j] = v[j] - lse;
}

// ---------------- launcher --------------------------------------------------
extern "C" void kernel_launch(void* const* d_in, const int* in_sizes, int n_in,
                              void* d_out, int out_size) {
    const float* x   = (const float*)d_in[0];
    const void*  ei  = d_in[1];               // [2, E], int32 or int64 (detected)
    const float* W1  = (const float*)d_in[2];
    const float* b1  = (const float*)d_in[3];
    const float* W2  = (const float*)d_in[4];
    const float* b2  = (const float*)d_in[5];
    float*       out = (float*)d_out;

    const int n  = in_sizes[0] / 64;   // 50000
    const int e2 = in_sizes[1];        // 2*E elements
    const int e  = e2 / 2;             // 800000

    // normalize edge indices to int32
    k_flag_init<<<1, 1>>>();
    k_detect <<<(e2 / 2 + 255) / 256, 256>>>((const unsigned*)ei, e2);
    k_convert<<<(e2 + 255) / 256, 256>>>(ei, e2);

    // degree / norm
    k_deg_init <<<(n + 255) / 256, 256>>>(n);
    k_deg_count<<<(e + 255) / 256, 256>>>(e);
    k_deg_rsqrt<<<(n + 255) / 256, 256>>>(n);

    // layer 1
    k_gemm1<<<(n + 63) / 64, 256>>>(x, W1, n);
    k_agg1_init<<<(n * 64 + 255) / 256, 256>>>(n);
    {
        long long threads = (long long)e * 16;
        k_scatter1<<<(int)((threads + 255) / 256), 256>>>(e);
    }

    // layer 2
    k_gemm2<<<(n + 15) / 16, 256>>>(b1, W2, n);
    k_agg2_init<<<(n * 16 + 255) / 256, 256>>>(n);
    {
        long long threads = (long long)e * 4;
        k_scatter2<<<(int)((threads + 255) / 256), 256>>>(e);
    }

    // epilogue
    k_logsoftmax<<<(n + 255) / 256, 256>>>(b2, out, n);
}

// round 4
// speedup vs baseline: 1.7959x; 1.7959x over previous
#include <cuda_runtime.h>
#include <math.h>

// Problem constants (fixed by the dataset)
constexpr int NN = 50000;   // nodes
constexpr int EE = 800000;  // edges

// ---------------- scratch (static __device__ — no allocation) --------------
__device__ float g_dinv[NN];            // rsqrt(deg+1)
__device__ float g_xl  [NN * 64];       // x @ W1
__device__ float g_agg [NN * 64];       // layer-1 aggregate (pre-relu, pre-b1)
__device__ float g_l   [NN * 16];       // relu(h) @ W2, padded 10->16
__device__ int   g_eidx[2 * EE];        // normalized int32 [src | dst]
__device__ int   g_deg [NN];            // in-degree (no self-loop)
__device__ int   g_rowstart[NN + 1];    // CSR row offsets (by dst)
__device__ int   g_cursor[NN];          // fill cursors
__device__ int   g_csr_src[EE];         // CSR adjacency: src ids grouped by dst
__device__ int   g_bsum[256];           // scan block sums
__device__ unsigned g_is32;             // 1 if edge_index is int32

// ---------------- edge-index dtype detect + normalize ----------------------
__global__ void k_flag_init() { g_is32 = 0u; }

// For int64 input the odd 32-bit words are hi-words == 0 (ids < 50000);
// for int32 input odd words are random node ids -> some nonzero.
__global__ void k_detect(const unsigned* __restrict__ p, int e2) {
    int i = blockIdx.x * blockDim.x + threadIdx.x;
    if (i < e2 / 2) {
        if (p[2 * i + 1] != 0u) atomicOr(&g_is32, 1u);
    }
}

__global__ void k_convert(const void* __restrict__ p, int e2) {
    int i = blockIdx.x * blockDim.x + threadIdx.x;
    if (i >= e2) return;
    if (g_is32) g_eidx[i] = ((const int*)p)[i];
    else        g_eidx[i] = (int)((const long long*)p)[i];
}

// ---------------- CSR build -------------------------------------------------
__global__ void k_zero(int n) {
    int i = blockIdx.x * blockDim.x + threadIdx.x;
    if (i < n) { g_deg[i] = 0; g_cursor[i] = 0; }
}

__global__ void k_hist(int e) {
    int i = blockIdx.x * blockDim.x + threadIdx.x;
    if (i < e) atomicAdd(&g_deg[g_eidx[e + i]], 1);
}

__device__ __forceinline__ int warp_incl_scan(int v) {
    int lane = threadIdx.x & 31;
#pragma unroll
    for (int o = 1; o < 32; o <<= 1) {
        int t = __shfl_up_sync(0xffffffffu, v, o);
        if (lane >= o) v += t;
    }
    return v;
}

// per-256-block exclusive scan of g_deg -> g_rowstart (block-local), totals -> g_bsum
__global__ void k_scan_block(int n) {
    __shared__ int wsum[8];
    int i = blockIdx.x * 256 + threadIdx.x;
    int v = (i < n) ? g_deg[i] : 0;
    int inc = warp_incl_scan(v);
    int lane = threadIdx.x & 31, w = threadIdx.x >> 5;
    if (lane == 31) wsum[w] = inc;
    __syncthreads();
    if (w == 0) {
        int s = (lane < 8) ? wsum[lane] : 0;
        int si = warp_incl_scan(s);
        if (lane < 8) wsum[lane] = si - s;  // exclusive warp offsets
    }
    __syncthreads();
    int exc = inc - v + wsum[w];
    if (i < n) g_rowstart[i] = exc;
    if (threadIdx.x == 255) g_bsum[blockIdx.x] = exc + v;  // block total
}

// scan the block sums (nb <= 256), one block
__global__ void k_scan_tops(int nb) {
    __shared__ int wsum[8];
    int t = threadIdx.x;
    int v = (t < nb) ? g_bsum[t] : 0;
    int inc = warp_incl_scan(v);
    int lane = t & 31, w = t >> 5;
    if (lane == 31) wsum[w] = inc;
    __syncthreads();
    if (w == 0) {
        int s = (lane < 8) ? wsum[lane] : 0;
        int si = warp_incl_scan(s);
        if (lane < 8) wsum[lane] = si - s;
    }
    __syncthreads();
    if (t < nb) g_bsum[t] = inc - v + wsum[w];  // exclusive
}

__global__ void k_scan_add(int n, int e) {
    int i = blockIdx.x * blockDim.x + threadIdx.x;
    if (i < n) g_rowstart[i] += g_bsum[i >> 8];
    if (i == 0) g_rowstart[n] = e;
}

__global__ void k_dinv(int n) {
    int i = blockIdx.x * blockDim.x + threadIdx.x;
    if (i < n) g_dinv[i] = rsqrtf((float)(g_deg[i] + 1));
}

__global__ void k_fill(int e) {
    int i = blockIdx.x * blockDim.x + threadIdx.x;
    if (i >= e) return;
    int d = g_eidx[e + i];
    int pos = atomicAdd(&g_cursor[d], 1);
    g_csr_src[g_rowstart[d] + pos] = g_eidx[i];
}

// ---------------- GEMM1: xl = x @ W1  (n x 64) @ (64 x 64) ----------------
__global__ __launch_bounds__(256) void k_gemm1(const float* __restrict__ x,
                                               const float* __restrict__ W,
                                               int n) {
    __shared__ float As[64 * 65];
    __shared__ float Bs[64 * 64];
    const int tid = threadIdx.x;
    const int row0 = blockIdx.x * 64;

    for (int i = tid; i < 4096; i += 256) Bs[i] = W[i];
    for (int i = tid; i < 4096; i += 256) {
        int r = i >> 6, k = i & 63;
        int gr = row0 + r;
        As[r * 65 + k] = (gr < n) ? x[gr * 64 + k] : 0.0f;
    }
    __syncthreads();

    const int tx = tid & 15;
    const int ty = tid >> 4;

    float acc[4][4];
#pragma unroll
    for (int i = 0; i < 4; i++)
#pragma unroll
        for (int j = 0; j < 4; j++) acc[i][j] = 0.0f;

#pragma unroll
    for (int k = 0; k < 64; k++) {
        float4 b = *(const float4*)&Bs[k * 64 + tx * 4];
        float a[4];
#pragma unroll
        for (int i = 0; i < 4; i++) a[i] = As[(ty * 4 + i) * 65 + k];
#pragma unroll
        for (int i = 0; i < 4; i++) {
            acc[i][0] = fmaf(a[i], b.x, acc[i][0]);
            acc[i][1] = fmaf(a[i], b.y, acc[i][1]);
            acc[i][2] = fmaf(a[i], b.z, acc[i][2]);
            acc[i][3] = fmaf(a[i], b.w, acc[i][3]);
        }
    }

#pragma unroll
    for (int i = 0; i < 4; i++) {
        int r = row0 + ty * 4 + i;
        if (r < n) {
            float4 v = make_float4(acc[i][0], acc[i][1], acc[i][2], acc[i][3]);
            *(float4*)&g_xl[r * 64 + tx * 4] = v;
        }
    }
}

// ---------------- layer-1 gather: one warp per dst node --------------------
// agg[d] = dinv[d] * ( dinv[d]*xl[d] + sum_{s in N(d)} dinv[s]*xl[s] )
__global__ __launch_bounds__(256) void k_gather1(int n) {
    int gw = (blockIdx.x * 256 + threadIdx.x) >> 5;
    int lane = threadIdx.x & 31;
    if (gw >= n) return;
    int beg = g_rowstart[gw], end = g_rowstart[gw + 1];
    float di = g_dinv[gw];
    const float2* xl2 = (const float2*)g_xl;

    float2 a = xl2[gw * 32 + lane];
    float2 acc = make_float2(a.x * di, a.y * di);  // self-loop (x di at end)

    int j = beg;
    int s = (j < end) ? g_csr_src[j] : 0;
    while (j < end) {
        int s_next = (j + 1 < end) ? g_csr_src[j + 1] : 0;
        float w = g_dinv[s];
        float2 v = xl2[s * 32 + lane];
        acc.x = fmaf(v.x, w, acc.x);
        acc.y = fmaf(v.y, w, acc.y);
        s = s_next;
        ++j;
    }
    acc.x *= di; acc.y *= di;
    ((float2*)g_agg)[gw * 32 + lane] = acc;
}

// ---------------- GEMM2 fused relu+b1: l = relu(agg + b1) @ W2 -------------
__global__ __launch_bounds__(256) void k_gemm2(const float* __restrict__ b1,
                                               const float* __restrict__ W2,
                                               int n) {
    __shared__ float Hs[16 * 64];
    __shared__ float W2s[64 * 16];
    const int tid = threadIdx.x;
    const int node0 = blockIdx.x * 16;

    for (int i = tid; i < 64 * 16; i += 256) {
        int k = i >> 4, j = i & 15;
        W2s[i] = (j < 10) ? W2[k * 10 + j] : 0.0f;
    }
    for (int i = tid; i < 16 * 64; i += 256) {
        int g = i >> 6, k = i & 63;
        int r = node0 + g;
        float v = 0.0f;
        if (r < n) v = fmaxf(g_agg[r * 64 + k] + b1[k], 0.0f);
        Hs[i] = v;
    }
    __syncthreads();

    const int g = tid >> 4;
    const int j = tid & 15;
    int r = node0 + g;
    if (r >= n) return;

    float acc = 0.0f;
#pragma unroll
    for (int k = 0; k < 64; k++) acc = fmaf(Hs[g * 64 + k], W2s[k * 16 + j], acc);
    g_l[r * 16 + j] = acc;
}

// ---------------- layer-2 gather + b2 + log_softmax (fused) ----------------
// 16 threads per node; width-16 shuffle reductions for max / sum.
__global__ __launch_bounds__(256) void k_gather2_softmax(const float* __restrict__ b2,
                                                         float* __restrict__ out,
                                                         int n) {
    int t = blockIdx.x * 256 + threadIdx.x;
    int nd = t >> 4;
    if (nd >= n) return;
    int c = t & 15;

    int beg = g_rowstart[nd], end = g_rowstart[nd + 1];
    float di = g_dinv[nd];
    float acc = g_l[nd * 16 + c] * di;  // self-loop

    int j = beg;
    int s = (j < end) ? g_csr_src[j] : 0;
    while (j < end) {
        int s_next = (j + 1 < end) ? g_csr_src[j + 1] : 0;
        acc = fmaf(g_l[s * 16 + c], g_dinv[s], acc);
        s = s_next;
        ++j;
    }
    acc *= di;

    float v = (c < 10) ? acc + b2[c] : -1e30f;
    float m = v;
#pragma unroll
    for (int o = 8; o > 0; o >>= 1) m = fmaxf(m, __shfl_xor_sync(0xffffffffu, m, o, 16));
    float ex = (c < 10) ? __expf(v - m) : 0.0f;
    float ssum = ex;
#pragma unroll
    for (int o = 8; o > 0; o >>= 1) ssum += __shfl_xor_sync(0xffffffffu, ssum, o, 16);
    float lse = m + __logf(ssum);
    if (c < 10) out[nd * 10 + c] = v - lse;
}

// ---------------- launcher --------------------------------------------------
extern "C" void kernel_launch(void* const* d_in, const int* in_sizes, int n_in,
                              void* d_out, int out_size) {
    const float* x   = (const float*)d_in[0];
    const void*  ei  = d_in[1];               // [2, E], int32 or int64 (detected)
    const float* W1  = (const float*)d_in[2];
    const float* b1  = (const float*)d_in[3];
    const float* W2  = (const float*)d_in[4];
    const float* b2  = (const float*)d_in[5];
    float*       out = (float*)d_out;

    const int n  = in_sizes[0] / 64;   // 50000
    const int e2 = in_sizes[1];        // 2*E elements
    const int e  = e2 / 2;             // 800000
    const int nb = (n + 255) / 256;    // scan blocks (196 <= 256)

    // normalize edge indices to int32
    k_flag_init<<<1, 1>>>();
    k_detect <<<(e2 / 2 + 255) / 256, 256>>>((const unsigned*)ei, e2);
    k_convert<<<(e2 + 255) / 256, 256>>>(ei, e2);

    // CSR build (by dst) + dinv
    k_zero<<<nb, 256>>>(n);
    k_hist<<<(e + 255) / 256, 256>>>(e);
    k_scan_block<<<nb, 256>>>(n);
    k_scan_tops<<<1, 256>>>(nb);
    k_scan_add<<<nb, 256>>>(n, e);
    k_dinv<<<nb, 256>>>(n);
    k_fill<<<(e + 255) / 256, 256>>>(e);

    // layer 1
    k_gemm1<<<(n + 63) / 64, 256>>>(x, W1, n);
    k_gather1<<<(n * 32 + 255) / 256, 256>>>(n);

    // layer 2 (+ fused epilogue)
    k_gemm2<<<(n + 15) / 16, 256>>>(b1, W2, n);
    k_gather2_softmax<<<(n * 16 + 255) / 256, 256>>>(b2, out, n);
}

// round 8
// speedup vs baseline: 2.2296x; 1.2415x over previous
#include <cuda_runtime.h>
#include <math.h>

// Problem constants (fixed by the dataset)
constexpr int NN = 50000;   // nodes
constexpr int EE = 800000;  // edges

// ---------------- scratch (static __device__ — no allocation) --------------
__device__ float g_dinv[NN];            // rsqrt(deg+1)
__device__ float g_xl  [NN * 64];       // x @ W1
__device__ float g_agg [NN * 64];       // layer-1 aggregate (pre-relu, pre-b1)
__device__ float g_l   [NN * 16];       // relu(h) @ W2, padded 10->16
__device__ int   g_eidx[2 * EE];        // normalized int32 [src | dst]
__device__ int   g_deg [NN];            // in-degree (no self-loop)
__device__ int   g_rowstart[NN + 1];    // CSR row offsets (by dst)
__device__ int   g_cursor[NN];          // fill cursors (init = rowstart)
__device__ int   g_csr_src[EE];         // CSR adjacency: src ids grouped by dst
__device__ int   g_bsum[256];           // scan block sums
__device__ unsigned g_is32;             // 1 if edge_index is int32

// ---------------- init: zero deg everywhere; block 0 detects dtype ---------
// For int64 input the odd 32-bit words are hi-words == 0 (ids < 50000);
// for int32 input odd words are random node ids. Sampling 4096 odd words
// gives P(misdetect) ~ (1/50000)^4096 ~ 0.
__global__ void k_init(const unsigned* __restrict__ p, int n, int e2) {
    int i = blockIdx.x * blockDim.x + threadIdx.x;
    if (i < n) g_deg[i] = 0;

    if (blockIdx.x == 0) {
        __shared__ unsigned flag;
        if (threadIdx.x == 0) flag = 0u;
        __syncthreads();
        int nsamp = e2 / 2 < 4096 ? e2 / 2 : 4096;
        unsigned f = 0u;
        for (int j = threadIdx.x; j < nsamp; j += 256) f |= p[2 * j + 1];
        if (f) atomicOr(&flag, 1u);
        __syncthreads();
        if (threadIdx.x == 0) g_is32 = flag ? 1u : 0u;
    }
}

// ---------------- convert to int32 + degree histogram ----------------------
__global__ void k_convert_hist(const void* __restrict__ p, int e2) {
    int i = blockIdx.x * blockDim.x + threadIdx.x;
    if (i >= e2) return;
    int v;
    if (g_is32) v = ((const int*)p)[i];
    else        v = (int)((const long long*)p)[i];
    g_eidx[i] = v;
    if (i >= e2 / 2) atomicAdd(&g_deg[v], 1);  // dst half -> degree
}

// ---------------- scan helpers ---------------------------------------------
__device__ __forceinline__ int warp_incl_scan(int v) {
    int lane = threadIdx.x & 31;
#pragma unroll
    for (int o = 1; o < 32; o <<= 1) {
        int t = __shfl_up_sync(0xffffffffu, v, o);
        if (lane >= o) v += t;
    }
    return v;
}

// per-256-block exclusive scan of deg -> rowstart(partial); totals -> bsum; dinv
__global__ void k_scan_block(int n) {
    __shared__ int wsum[8];
    int i = blockIdx.x * 256 + threadIdx.x;
    int v = (i < n) ? g_deg[i] : 0;
    if (i < n) g_dinv[i] = rsqrtf((float)(v + 1));
    int inc = warp_incl_scan(v);
    int lane = threadIdx.x & 31, w = threadIdx.x >> 5;
    if (lane == 31) wsum[w] = inc;
    __syncthreads();
    if (w == 0) {
        int s = (lane < 8) ? wsum[lane] : 0;
        int si = warp_incl_scan(s);
        if (lane < 8) wsum[lane] = si - s;
    }
    __syncthreads();
    int exc = inc - v + wsum[w];
    if (i < n) g_rowstart[i] = exc;
    if (threadIdx.x == 255) g_bsum[blockIdx.x] = exc + v;
}

__global__ void k_scan_tops(int nb) {
    __shared__ int wsum[8];
    int t = threadIdx.x;
    int v = (t < nb) ? g_bsum[t] : 0;
    int inc = warp_incl_scan(v);
    int lane = t & 31, w = t >> 5;
    if (lane == 31) wsum[w] = inc;
    __syncthreads();
    if (w == 0) {
        int s = (lane < 8) ? wsum[lane] : 0;
        int si = warp_incl_scan(s);
        if (lane < 8) wsum[lane] = si - s;
    }
    __syncthreads();
    if (t < nb) g_bsum[t] = inc - v + wsum[w];
}

__global__ void k_scan_add(int n, int e) {
    int i = blockIdx.x * blockDim.x + threadIdx.x;
    if (i < n) {
        int r = g_rowstart[i] + g_bsum[i >> 8];
        g_rowstart[i] = r;
        g_cursor[i] = r;   // fill cursors start at row base
    }
    if (i == 0) g_rowstart[n] = e;
}

__global__ void k_fill(int e) {
    int i = blockIdx.x * blockDim.x + threadIdx.x;
    if (i >= e) return;
    int d = g_eidx[e + i];
    int pos = atomicAdd(&g_cursor[d], 1);
    g_csr_src[pos] = g_eidx[i];
}

// ---------------- GEMM1: xl = x @ W1  (n x 64) @ (64 x 64) ----------------
__global__ __launch_bounds__(256) void k_gemm1(const float* __restrict__ x,
                                               const float* __restrict__ W,
                                               int n) {
    __shared__ float As[64 * 65];
    __shared__ float Bs[64 * 64];
    const int tid = threadIdx.x;
    const int row0 = blockIdx.x * 64;

    for (int i = tid; i < 4096; i += 256) Bs[i] = W[i];
    for (int i = tid; i < 4096; i += 256) {
        int r = i >> 6, k = i & 63;
        int gr = row0 + r;
        As[r * 65 + k] = (gr < n) ? x[gr * 64 + k] : 0.0f;
    }
    __syncthreads();

    const int tx = tid & 15;
    const int ty = tid >> 4;

    float acc[4][4];
#pragma unroll
    for (int i = 0; i < 4; i++)
#pragma unroll
        for (int j = 0; j < 4; j++) acc[i][j] = 0.0f;

#pragma unroll
    for (int k = 0; k < 64; k++) {
        float4 b = *(const float4*)&Bs[k * 64 + tx * 4];
        float a[4];
#pragma unroll
        for (int i = 0; i < 4; i++) a[i] = As[(ty * 4 + i) * 65 + k];
#pragma unroll
        for (int i = 0; i < 4; i++) {
            acc[i][0] = fmaf(a[i], b.x, acc[i][0]);
            acc[i][1] = fmaf(a[i], b.y, acc[i][1]);
            acc[i][2] = fmaf(a[i], b.z, acc[i][2]);
            acc[i][3] = fmaf(a[i], b.w, acc[i][3]);
        }
    }

#pragma unroll
    for (int i = 0; i < 4; i++) {
        int r = row0 + ty * 4 + i;
        if (r < n) {
            float4 v = make_float4(acc[i][0], acc[i][1], acc[i][2], acc[i][3]);
            *(float4*)&g_xl[r * 64 + tx * 4] = v;
        }
    }
}

// ---------------- layer-1 gather: 16 threads/node, float4/lane -------------
// agg[d] = dinv[d] * ( dinv[d]*xl[d] + sum_{s in N(d)} dinv[s]*xl[s] )
__global__ __launch_bounds__(256) void k_gather1(int n) {
    int t = blockIdx.x * 256 + threadIdx.x;
    int nd = t >> 4;
    if (nd >= n) return;
    int c = t & 15;

    int beg = g_rowstart[nd], end = g_rowstart[nd + 1];
    float di = g_dinv[nd];
    const float4* xl4 = (const float4*)g_xl;

    float4 a = xl4[nd * 16 + c];
    float4 acc = make_float4(a.x * di, a.y * di, a.z * di, a.w * di);

    int j = beg;
    for (; j + 1 < end; j += 2) {
        int s0 = g_csr_src[j];
        int s1 = g_csr_src[j + 1];
        float w0 = g_dinv[s0];
        float w1 = g_dinv[s1];
        float4 v0 = xl4[s0 * 16 + c];
        float4 v1 = xl4[s1 * 16 + c];
        acc.x = fmaf(v0.x, w0, acc.x); acc.y = fmaf(v0.y, w0, acc.y);
        acc.z = fmaf(v0.z, w0, acc.z); acc.w = fmaf(v0.w, w0, acc.w);
        acc.x = fmaf(v1.x, w1, acc.x); acc.y = fmaf(v1.y, w1, acc.y);
        acc.z = fmaf(v1.z, w1, acc.z); acc.w = fmaf(v1.w, w1, acc.w);
    }
    if (j < end) {
        int s0 = g_csr_src[j];
        float w0 = g_dinv[s0];
        float4 v0 = xl4[s0 * 16 + c];
        acc.x = fmaf(v0.x, w0, acc.x); acc.y = fmaf(v0.y, w0, acc.y);
        acc.z = fmaf(v0.z, w0, acc.z); acc.w = fmaf(v0.w, w0, acc.w);
    }
    acc.x *= di; acc.y *= di; acc.z *= di; acc.w *= di;
    ((float4*)g_agg)[nd * 16 + c] = acc;
}

// ---------------- GEMM2 fused relu+b1: l = relu(agg + b1) @ W2 -------------
__global__ __launch_bounds__(256) void k_gemm2(const float* __restrict__ b1,
                                               const float* __restrict__ W2,
                                               int n) {
    __shared__ float Hs[16 * 64];
    __shared__ float W2s[64 * 16];
    const int tid = threadIdx.x;
    const int node0 = blockIdx.x * 16;

    for (int i = tid; i < 64 * 16; i += 256) {
        int k = i >> 4, j = i & 15;
        W2s[i] = (j < 10) ? W2[k * 10 + j] : 0.0f;
    }
    for (int i = tid; i < 16 * 64; i += 256) {
        int g = i >> 6, k = i & 63;
        int r = node0 + g;
        float v = 0.0f;
        if (r < n) v = fmaxf(g_agg[r * 64 + k] + b1[k], 0.0f);
        Hs[i] = v;
    }
    __syncthreads();

    const int g = tid >> 4;
    const int j = tid & 15;
    int r = node0 + g;
    if (r >= n) return;

    float acc = 0.0f;
#pragma unroll
    for (int k = 0; k < 64; k++) acc = fmaf(Hs[g * 64 + k], W2s[k * 16 + j], acc);
    g_l[r * 16 + j] = acc;
}

// ---------------- layer-2 gather + b2 + log_softmax (fused) ----------------
__global__ __launch_bounds__(256) void k_gather2_softmax(const float* __restrict__ b2,
                                                         float* __restrict__ out,
                                                         int n) {
    int t = blockIdx.x * 256 + threadIdx.x;
    int nd = t >> 4;
    if (nd >= n) return;
    int c = t & 15;

    int beg = g_rowstart[nd], end = g_rowstart[nd + 1];
    float di = g_dinv[nd];
    float acc = g_l[nd * 16 + c] * di;

    int j = beg;
    for (; j + 1 < end; j += 2) {
        int s0 = g_csr_src[j];
        int s1 = g_csr_src[j + 1];
        float w0 = g_dinv[s0];
        float w1 = g_dinv[s1];
        float v0 = g_l[s0 * 16 + c];
        float v1 = g_l[s1 * 16 + c];
        acc = fmaf(v0, w0, acc);
        acc = fmaf(v1, w1, acc);
    }
    if (j < end) {
        int s0 = g_csr_src[j];
        acc = fmaf(g_l[s0 * 16 + c], g_dinv[s0], acc);
    }
    acc *= di;

    float v = (c < 10) ? acc + b2[c] : -1e30f;
    float m = v;
#pragma unroll
    for (int o = 8; o > 0; o >>= 1) m = fmaxf(m, __shfl_xor_sync(0xffffffffu, m, o, 16));
    float ex = (c < 10) ? __expf(v - m) : 0.0f;
    float ssum = ex;
#pragma unroll
    for (int o = 8; o > 0; o >>= 1) ssum += __shfl_xor_sync(0xffffffffu, ssum, o, 16);
    float lse = m + __logf(ssum);
    if (c < 10) out[nd * 10 + c] = v - lse;
}

// ---------------- launcher --------------------------------------------------
extern "C" void kernel_launch(void* const* d_in, const int* in_sizes, int n_in,
                              void* d_out, int out_size) {
    const float* x   = (const float*)d_in[0];
    const void*  ei  = d_in[1];               // [2, E], int32 or int64 (detected)
    const float* W1  = (const float*)d_in[2];
    const float* b1  = (const float*)d_in[3];
    const float* W2  = (const float*)d_in[4];
    const float* b2  = (const float*)d_in[5];
    float*       out = (float*)d_out;

    const int n  = in_sizes[0] / 64;   // 50000
    const int e2 = in_sizes[1];        // 2*E elements
    const int e  = e2 / 2;             // 800000
    const int nb = (n + 255) / 256;    // scan blocks (196 <= 256)

    // setup: dtype detect + deg zero | convert+hist | scan | fill
    k_init        <<<nb, 256>>>((const unsigned*)ei, n, e2);
    k_convert_hist<<<(e2 + 255) / 256, 256>>>(ei, e2);
    k_scan_block  <<<nb, 256>>>(n);
    k_scan_tops   <<<1, 256>>>(nb);
    k_scan_add    <<<nb, 256>>>(n, e);
    k_fill        <<<(e + 255) / 256, 256>>>(e);

    // layer 1
    k_gemm1  <<<(n + 63) / 64, 256>>>(x, W1, n);
    k_gather1<<<(n * 16 + 255) / 256, 256>>>(n);

    // layer 2 (+ fused epilogue)
    k_gemm2           <<<(n + 15) / 16, 256>>>(b1, W2, n);
    k_gather2_softmax <<<(n * 16 + 255) / 256, 256>>>(b2, out, n);
}

// round 11
// speedup vs baseline: 2.2528x; 1.0104x over previous
#include <cuda_runtime.h>
#include <math.h>

// Problem constants (fixed by the dataset)
constexpr int NN = 50000;   // nodes
constexpr int EE = 800000;  // edges

// ---------------- scratch (static __device__ — no allocation) --------------
__device__ float g_dinv[NN];             // rsqrt(deg+1)
__device__ float g_xl  [NN * 64];        // x @ W1
__device__ float g_l   [NN * 16];        // relu(h) @ W2, padded 10->16
__device__ int   g_eidx[2 * EE];         // normalized int32 [src | dst]
__device__ int   g_deg [NN];             // in-degree (zero at entry; re-zeroed by k_fill)
__device__ int   g_rowstart[NN + 1];     // CSR row offsets (by dst)
__device__ int   g_cursor[NN];           // fill cursors (init = rowstart)
__device__ int   g_csr_src[EE];          // CSR adjacency: src ids grouped by dst
__device__ unsigned long long g_status[256];  // lookback scan status (flag<<32 | value)

// ---------------- convert to int32 + degree histogram + status reset -------
// Per-block dtype detection: sample 256 odd 32-bit words. For int64 input all
// are hi-words == 0 (ids < 50000); for int32 they are random node ids.
__global__ void k_convert_hist(const void* __restrict__ p, int e2) {
    const int tid = threadIdx.x;

    if (blockIdx.x == 0) g_status[tid] = 0ULL;  // reset scan statuses

    unsigned f = 0u;
    int nsamp = (e2 / 2 < 256) ? e2 / 2 : 256;
    if (tid < nsamp) f = ((const unsigned*)p)[2 * tid + 1];
    int is32 = __syncthreads_or(f != 0u);

    int i = blockIdx.x * 256 + tid;
    if (i >= e2) return;
    int v;
    if (is32) v = ((const int*)p)[i];
    else      v = (int)((const long long*)p)[i];
    g_eidx[i] = v;
    if (i >= e2 / 2) atomicAdd(&g_deg[v], 1);  // dst half -> degree
}

// ---------------- single-kernel exclusive scan (decoupled lookback) --------
// Computes rowstart (exclusive prefix of deg), cursor (= rowstart), dinv.
__device__ __forceinline__ int warp_incl_scan(int v) {
    int lane = threadIdx.x & 31;
#pragma unroll
    for (int o = 1; o < 32; o <<= 1) {
        int t = __shfl_up_sync(0xffffffffu, v, o);
        if (lane >= o) v += t;
    }
    return v;
}

__global__ __launch_bounds__(256) void k_scan(int n, int e) {
    __shared__ int wsum[8];
    __shared__ int s_prefix, s_total;
    const int tid = threadIdx.x;
    const int b = blockIdx.x;
    const int i = b * 256 + tid;

    int v = (i < n) ? g_deg[i] : 0;
    if (i < n) g_dinv[i] = rsqrtf((float)(v + 1));

    // block-wide inclusive scan
    int inc = warp_incl_scan(v);
    int lane = tid & 31, w = tid >> 5;
    if (lane == 31) wsum[w] = inc;
    __syncthreads();
    if (w == 0) {
        int s = (lane < 8) ? wsum[lane] : 0;
        int si = warp_incl_scan(s);
        if (lane < 8) wsum[lane] = si - s;
    }
    __syncthreads();
    inc += wsum[w];                 // block-local inclusive
    if (tid == 255) s_total = inc;  // block total
    __syncthreads();
    int total = s_total;

    // post aggregate (block 0: it's already the inclusive prefix)
    if (tid == 0) {
        unsigned long long pack =
            ((unsigned long long)(b == 0 ? 2u : 1u) << 32) | (unsigned)total;
        atomicExch(&g_status[b], pack);
    }

    // warp-parallel lookback
    if (b == 0) {
        if (tid == 0) s_prefix = 0;
    } else if (tid < 32) {
        int prefix = 0;
        int look = b - 1;
        while (true) {
            int idx = look - tid;
            unsigned long long st;
            unsigned flag;
            do {
                st = (idx >= 0) ? *((volatile unsigned long long*)&g_status[idx])
                                : (2ULL << 32);
                flag = (unsigned)(st >> 32);
            } while (__any_sync(0xffffffffu, flag == 0u));
            int val = (int)(st & 0xffffffffULL);
            unsigned ball = __ballot_sync(0xffffffffu, flag == 2u);
            if (ball) {
                int fi = __ffs(ball) - 1;          // nearest inclusive entry
                int contrib = (tid <= fi) ? val : 0;
#pragma unroll
                for (int o = 16; o; o >>= 1)
                    contrib += __shfl_down_sync(0xffffffffu, contrib, o);
                if (tid == 0) prefix += contrib;
                break;
            } else {
                int contrib = val;
#pragma unroll
                for (int o = 16; o; o >>= 1)
                    contrib += __shfl_down_sync(0xffffffffu, contrib, o);
                if (tid == 0) prefix += contrib;
                look -= 32;
            }
        }
        if (tid == 0) s_prefix = prefix;
    }
    __syncthreads();
    int prefix = s_prefix;

    // upgrade to inclusive
    if (b != 0 && tid == 0) {
        unsigned long long pack = (2ULL << 32) | (unsigned)(prefix + total);
        atomicExch(&g_status[b], pack);
    }

    int exc = prefix + inc - v;
    if (i < n) { g_rowstart[i] = exc; g_cursor[i] = exc; }
    if (b == 0 && tid == 0) g_rowstart[n] = e;
}

// ---------------- CSR fill (+ re-zero deg for next invocation) -------------
__global__ void k_fill(int n, int e) {
    int i = blockIdx.x * blockDim.x + threadIdx.x;
    if (i < n) g_deg[i] = 0;          // restore invariant for next call
    if (i >= e) return;
    int d = g_eidx[e + i];
    int pos = atomicAdd(&g_cursor[d], 1);
    g_csr_src[pos] = g_eidx[i];
}

// ---------------- GEMM1: xl = x @ W1  (n x 64) @ (64 x 64) ----------------
__global__ __launch_bounds__(256) void k_gemm1(const float* __restrict__ x,
                                               const float* __restrict__ W,
                                               int n) {
    __shared__ float As[64 * 65];
    __shared__ float Bs[64 * 64];
    const int tid = threadIdx.x;
    const int row0 = blockIdx.x * 64;

    for (int i = tid; i < 4096; i += 256) Bs[i] = W[i];
    for (int i = tid; i < 4096; i += 256) {
        int r = i >> 6, k = i & 63;
        int gr = row0 + r;
        As[r * 65 + k] = (gr < n) ? x[gr * 64 + k] : 0.0f;
    }
    __syncthreads();

    const int tx = tid & 15;
    const int ty = tid >> 4;

    float acc[4][4];
#pragma unroll
    for (int i = 0; i < 4; i++)
#pragma unroll
        for (int j = 0; j < 4; j++) acc[i][j] = 0.0f;

#pragma unroll
    for (int k = 0; k < 64; k++) {
        float4 b = *(const float4*)&Bs[k * 64 + tx * 4];
        float a[4];
#pragma unroll
        for (int i = 0; i < 4; i++) a[i] = As[(ty * 4 + i) * 65 + k];
#pragma unroll
        for (int i = 0; i < 4; i++) {
            acc[i][0] = fmaf(a[i], b.x, acc[i][0]);
            acc[i][1] = fmaf(a[i], b.y, acc[i][1]);
            acc[i][2] = fmaf(a[i], b.z, acc[i][2]);
            acc[i][3] = fmaf(a[i], b.w, acc[i][3]);
        }
    }

#pragma unroll
    for (int i = 0; i < 4; i++) {
        int r = row0 + ty * 4 + i;
        if (r < n) {
            float4 v = make_float4(acc[i][0], acc[i][1], acc[i][2], acc[i][3]);
            *(float4*)&g_xl[r * 64 + tx * 4] = v;
        }
    }
}

// ---------------- fused: layer-1 gather + relu + b1 + GEMM2 ----------------
// 16 threads/node, float4/lane gather; epilogue through smem computes
// l[node] = relu(agg + b1) @ W2 (padded to 16 cols) without touching gmem.
__global__ __launch_bounds__(256) void k_gather1_gemm2(const float* __restrict__ b1,
                                                       const float* __restrict__ W2,
                                                       int n) {
    __shared__ float Hs[16 * 68];      // stride 68: conflict-free phase 2
    __shared__ float W2s[64 * 16];
    const int tid = threadIdx.x;

    for (int i = tid; i < 64 * 16; i += 256) {
        int k = i >> 4, j = i & 15;
        W2s[i] = (j < 10) ? W2[k * 10 + j] : 0.0f;
    }

    int t = blockIdx.x * 256 + tid;
    int nd = t >> 4;
    int c = t & 15;
    int g = tid >> 4;

    float4 hv = make_float4(0.f, 0.f, 0.f, 0.f);
    if (nd < n) {
        int beg = g_rowstart[nd], end = g_rowstart[nd + 1];
        float di = g_dinv[nd];
        const float4* xl4 = (const float4*)g_xl;

        float4 a = xl4[nd * 16 + c];
        float4 acc = make_float4(a.x * di, a.y * di, a.z * di, a.w * di);

        int j = beg;
        for (; j + 1 < end; j += 2) {
            int s0 = g_csr_src[j];
            int s1 = g_csr_src[j + 1];
            float w0 = g_dinv[s0];
            float w1 = g_dinv[s1];
            float4 v0 = xl4[s0 * 16 + c];
            float4 v1 = xl4[s1 * 16 + c];
            acc.x = fmaf(v0.x, w0, acc.x); acc.y = fmaf(v0.y, w0, acc.y);
            acc.z = fmaf(v0.z, w0, acc.z); acc.w = fmaf(v0.w, w0, acc.w);
            acc.x = fmaf(v1.x, w1, acc.x); acc.y = fmaf(v1.y, w1, acc.y);
            acc.z = fmaf(v1.z, w1, acc.z); acc.w = fmaf(v1.w, w1, acc.w);
        }
        if (j < end) {
            int s0 = g_csr_src[j];
            float w0 = g_dinv[s0];
            float4 v0 = xl4[s0 * 16 + c];
            acc.x = fmaf(v0.x, w0, acc.x); acc.y = fmaf(v0.y, w0, acc.y);
            acc.z = fmaf(v0.z, w0, acc.z); acc.w = fmaf(v0.w, w0, acc.w);
        }
        float4 bb = *(const float4*)&b1[c * 4];
        hv.x = fmaxf(fmaf(acc.x, di, bb.x) - bb.x + (acc.x * di + bb.x) - (acc.x * di), 0.0f);
        // (simple form below; line above avoided — keep it straightforward)
        hv.x = fmaxf(acc.x * di + bb.x, 0.0f);
        hv.y = fmaxf(acc.y * di + bb.y, 0.0f);
        hv.z = fmaxf(acc.z * di + bb.z, 0.0f);
        hv.w = fmaxf(acc.w * di + bb.w, 0.0f);
    }
    // stage relu'd features (stride 68 floats per node row)
    Hs[g * 68 + c * 4 + 0] = hv.x;
    Hs[g * 68 + c * 4 + 1] = hv.y;
    Hs[g * 68 + c * 4 + 2] = hv.z;
    Hs[g * 68 + c * 4 + 3] = hv.w;
    __syncthreads();

    // phase 2: l[r, j] = sum_k Hs[g,k] * W2s[k,j]
    int r = blockIdx.x * 16 + g;
    if (r >= n) return;
    int j = tid & 15;
    float accl = 0.0f;
#pragma unroll
    for (int k = 0; k < 64; k++) accl = fmaf(Hs[g * 68 + k], W2s[k * 16 + j], accl);
    g_l[r * 16 + j] = accl;
}

// ---------------- layer-2 gather + b2 + log_softmax (fused) ----------------
__global__ __launch_bounds__(256) void k_gather2_softmax(const float* __restrict__ b2,
                                                         float* __restrict__ out,
                                                         int n) {
    int t = blockIdx.x * 256 + threadIdx.x;
    int nd = t >> 4;
    if (nd >= n) return;
    int c = t & 15;

    int beg = g_rowstart[nd], end = g_rowstart[nd + 1];
    float di = g_dinv[nd];
    float acc = g_l[nd * 16 + c] * di;

    int j = beg;
    for (; j + 1 < end; j += 2) {
        int s0 = g_csr_src[j];
        int s1 = g_csr_src[j + 1];
        float w0 = g_dinv[s0];
        float w1 = g_dinv[s1];
        float v0 = g_l[s0 * 16 + c];
        float v1 = g_l[s1 * 16 + c];
        acc = fmaf(v0, w0, acc);
        acc = fmaf(v1, w1, acc);
    }
    if (j < end) {
        int s0 = g_csr_src[j];
        acc = fmaf(g_l[s0 * 16 + c], g_dinv[s0], acc);
    }
    acc *= di;

    float v = (c < 10) ? acc + b2[c] : -1e30f;
    float m = v;
#pragma unroll
    for (int o = 8; o > 0; o >>= 1) m = fmaxf(m, __shfl_xor_sync(0xffffffffu, m, o, 16));
    float ex = (c < 10) ? __expf(v - m) : 0.0f;
    float ssum = ex;
#pragma unroll
    for (int o = 8; o > 0; o >>= 1) ssum += __shfl_xor_sync(0xffffffffu, ssum, o, 16);
    float lse = m + __logf(ssum);
    if (c < 10) out[nd * 10 + c] = v - lse;
}

// ---------------- launcher --------------------------------------------------
extern "C" void kernel_launch(void* const* d_in, const int* in_sizes, int n_in,
                              void* d_out, int out_size) {
    const float* x   = (const float*)d_in[0];
    const void*  ei  = d_in[1];               // [2, E], int32 or int64 (detected)
    const float* W1  = (const float*)d_in[2];
    const float* b1  = (const float*)d_in[3];
    const float* W2  = (const float*)d_in[4];
    const float* b2  = (const float*)d_in[5];
    float*       out = (float*)d_out;

    const int n  = in_sizes[0] / 64;   // 50000
    const int e2 = in_sizes[1];        // 2*E elements
    const int e  = e2 / 2;             // 800000
    const int nb = (n + 255) / 256;    // 196 scan blocks (<=256 statuses)

    k_convert_hist   <<<(e2 + 255) / 256, 256>>>(ei, e2);
    k_scan           <<<nb, 256>>>(n, e);
    k_fill           <<<(e + 255) / 256, 256>>>(n, e);
    k_gemm1          <<<(n + 63) / 64, 256>>>(x, W1, n);
    k_gather1_gemm2  <<<(n * 16 + 255) / 256, 256>>>(b1, W2, n);
    k_gather2_softmax<<<(n * 16 + 255) / 256, 256>>>(b2, out, n);
}

// round 12
// speedup vs baseline: 2.3395x; 1.0385x over previous
#include <cuda_runtime.h>
#include <math.h>

// Problem constants (fixed by the dataset)
constexpr int NN = 50000;   // nodes
constexpr int EE = 800000;  // edges

// ---------------- scratch (static __device__ — no allocation) --------------
__device__ float g_dinv[NN];             // rsqrt(deg+1)
__device__ float g_xl  [NN * 64];        // x @ W1
__device__ float g_l   [NN * 16];        // relu(h) @ W2, padded 10->16
__device__ int   g_eidx[2 * EE];         // normalized int32 [src | dst]
__device__ int   g_deg [NN];             // in-degree (zero at entry; re-zeroed by k_fill)
__device__ int   g_rowstart[NN + 1];     // CSR row offsets (by dst)
__device__ int   g_cursor[NN];           // fill cursors (init = rowstart)
__device__ int   g_csr_src[EE];          // CSR adjacency: src ids grouped by dst
__device__ unsigned long long g_status[256];  // lookback scan status (flag<<32 | value)

// ---------------- convert to int32 + degree histogram + status reset -------
// Per-block dtype detection: sample 256 odd 32-bit words. For int64 input all
// are hi-words == 0 (ids < 50000); for int32 they are random node ids.
__global__ void k_convert_hist(const void* __restrict__ p, int e2) {
    const int tid = threadIdx.x;

    if (blockIdx.x == 0) g_status[tid] = 0ULL;  // reset scan statuses

    unsigned f = 0u;
    int nsamp = (e2 / 2 < 256) ? e2 / 2 : 256;
    if (tid < nsamp) f = ((const unsigned*)p)[2 * tid + 1];
    int is32 = __syncthreads_or(f != 0u);

    int i = blockIdx.x * 256 + tid;
    if (i >= e2) return;
    int v;
    if (is32) v = ((const int*)p)[i];
    else      v = (int)((const long long*)p)[i];
    g_eidx[i] = v;
    if (i >= e2 / 2) atomicAdd(&g_deg[v], 1);  // dst half -> degree
}

// ---------------- single-kernel exclusive scan (decoupled lookback) --------
__device__ __forceinline__ int warp_incl_scan(int v) {
    int lane = threadIdx.x & 31;
#pragma unroll
    for (int o = 1; o < 32; o <<= 1) {
        int t = __shfl_up_sync(0xffffffffu, v, o);
        if (lane >= o) v += t;
    }
    return v;
}

__global__ __launch_bounds__(256) void k_scan(int n, int e) {
    __shared__ int wsum[8];
    __shared__ int s_prefix, s_total;
    const int tid = threadIdx.x;
    const int b = blockIdx.x;
    const int i = b * 256 + tid;

    int v = (i < n) ? g_deg[i] : 0;
    if (i < n) g_dinv[i] = rsqrtf((float)(v + 1));

    // block-wide inclusive scan
    int inc = warp_incl_scan(v);
    int lane = tid & 31, w = tid >> 5;
    if (lane == 31) wsum[w] = inc;
    __syncthreads();
    if (w == 0) {
        int s = (lane < 8) ? wsum[lane] : 0;
        int si = warp_incl_scan(s);
        if (lane < 8) wsum[lane] = si - s;
    }
    __syncthreads();
    inc += wsum[w];
    if (tid == 255) s_total = inc;
    __syncthreads();
    int total = s_total;

    if (tid == 0) {
        unsigned long long pack =
            ((unsigned long long)(b == 0 ? 2u : 1u) << 32) | (unsigned)total;
        atomicExch(&g_status[b], pack);
    }

    if (b == 0) {
        if (tid == 0) s_prefix = 0;
    } else if (tid < 32) {
        int prefix = 0;
        int look = b - 1;
        while (true) {
            int idx = look - tid;
            unsigned long long st;
            unsigned flag;
            do {
                st = (idx >= 0) ? *((volatile unsigned long long*)&g_status[idx])
                                : (2ULL << 32);
                flag = (unsigned)(st >> 32);
            } while (__any_sync(0xffffffffu, flag == 0u));
            int val = (int)(st & 0xffffffffULL);
            unsigned ball = __ballot_sync(0xffffffffu, flag == 2u);
            if (ball) {
                int fi = __ffs(ball) - 1;
                int contrib = (tid <= fi) ? val : 0;
#pragma unroll
                for (int o = 16; o; o >>= 1)
                    contrib += __shfl_down_sync(0xffffffffu, contrib, o);
                if (tid == 0) prefix += contrib;
                break;
            } else {
                int contrib = val;
#pragma unroll
                for (int o = 16; o; o >>= 1)
                    contrib += __shfl_down_sync(0xffffffffu, contrib, o);
                if (tid == 0) prefix += contrib;
                look -= 32;
            }
        }
        if (tid == 0) s_prefix = prefix;
    }
    __syncthreads();
    int prefix = s_prefix;

    if (b != 0 && tid == 0) {
        unsigned long long pack = (2ULL << 32) | (unsigned)(prefix + total);
        atomicExch(&g_status[b], pack);
    }

    int exc = prefix + inc - v;
    if (i < n) { g_rowstart[i] = exc; g_cursor[i] = exc; }
    if (b == 0 && tid == 0) g_rowstart[n] = e;
}

// ---------------- CSR fill (+ re-zero deg for next invocation) -------------
__global__ void k_fill(int n, int e) {
    int i = blockIdx.x * blockDim.x + threadIdx.x;
    if (i < n) g_deg[i] = 0;
    if (i >= e) return;
    int d = g_eidx[e + i];
    int pos = atomicAdd(&g_cursor[d], 1);
    g_csr_src[pos] = g_eidx[i];
}

// ---------------- GEMM1: xl = x @ W1  (n x 64) @ (64 x 64) ----------------
// x tile stored TRANSPOSED in smem (At[k][r], row stride 68 floats = 272 B,
// 16B-aligned) so both operand fetches in the inner loop are LDS.128.
__global__ __launch_bounds__(256) void k_gemm1(const float* __restrict__ x,
                                               const float* __restrict__ W,
                                               int n) {
    __shared__ float At[64 * 68];  // [k][r] transposed x tile
    __shared__ float Bs[64 * 64];  // W1 [k][j]
    const int tid = threadIdx.x;
    const int row0 = blockIdx.x * 64;

    for (int i = tid; i < 4096; i += 256) Bs[i] = W[i];
    for (int i = tid; i < 4096; i += 256) {
        int r = i >> 6, k = i & 63;          // consecutive tid -> consecutive k (coalesced gmem)
        int gr = row0 + r;
        At[k * 68 + r] = (gr < n) ? x[gr * 64 + k] : 0.0f;
    }
    __syncthreads();

    const int tx = tid & 15;   // output col group (4 cols)
    const int ty = tid >> 4;   // output row group (4 rows)

    float acc[4][4];
#pragma unroll
    for (int i = 0; i < 4; i++)
#pragma unroll
        for (int j = 0; j < 4; j++) acc[i][j] = 0.0f;

#pragma unroll
    for (int k = 0; k < 64; k++) {
        float4 a = *(const float4*)&At[k * 68 + ty * 4];   // LDS.128
        float4 b = *(const float4*)&Bs[k * 64 + tx * 4];   // LDS.128
        acc[0][0] = fmaf(a.x, b.x, acc[0][0]); acc[0][1] = fmaf(a.x, b.y, acc[0][1]);
        acc[0][2] = fmaf(a.x, b.z, acc[0][2]); acc[0][3] = fmaf(a.x, b.w, acc[0][3]);
        acc[1][0] = fmaf(a.y, b.x, acc[1][0]); acc[1][1] = fmaf(a.y, b.y, acc[1][1]);
        acc[1][2] = fmaf(a.y, b.z, acc[1][2]); acc[1][3] = fmaf(a.y, b.w, acc[1][3]);
        acc[2][0] = fmaf(a.z, b.x, acc[2][0]); acc[2][1] = fmaf(a.z, b.y, acc[2][1]);
        acc[2][2] = fmaf(a.z, b.z, acc[2][2]); acc[2][3] = fmaf(a.z, b.w, acc[2][3]);
        acc[3][0] = fmaf(a.w, b.x, acc[3][0]); acc[3][1] = fmaf(a.w, b.y, acc[3][1]);
        acc[3][2] = fmaf(a.w, b.z, acc[3][2]); acc[3][3] = fmaf(a.w, b.w, acc[3][3]);
    }

#pragma unroll
    for (int i = 0; i < 4; i++) {
        int r = row0 + ty * 4 + i;
        if (r < n) {
            float4 v = make_float4(acc[i][0], acc[i][1], acc[i][2], acc[i][3]);
            *(float4*)&g_xl[r * 64 + tx * 4] = v;
        }
    }
}

// ---------------- fused: layer-1 gather + relu + b1 + GEMM2 ----------------
__global__ __launch_bounds__(256) void k_gather1_gemm2(const float* __restrict__ b1,
                                                       const float* __restrict__ W2,
                                                       int n) {
    __shared__ float Hs[16 * 68];
    __shared__ float W2s[64 * 16];
    const int tid = threadIdx.x;

    for (int i = tid; i < 64 * 16; i += 256) {
        int k = i >> 4, j = i & 15;
        W2s[i] = (j < 10) ? W2[k * 10 + j] : 0.0f;
    }

    int t = blockIdx.x * 256 + tid;
    int nd = t >> 4;
    int c = t & 15;
    int g = tid >> 4;

    float4 hv = make_float4(0.f, 0.f, 0.f, 0.f);
    if (nd < n) {
        int beg = g_rowstart[nd], end = g_rowstart[nd + 1];
        float di = g_dinv[nd];
        const float4* xl4 = (const float4*)g_xl;

        float4 a = xl4[nd * 16 + c];
        float4 acc = make_float4(a.x * di, a.y * di, a.z * di, a.w * di);

        int j = beg;
        for (; j + 1 < end; j += 2) {
            int s0 = g_csr_src[j];
            int s1 = g_csr_src[j + 1];
            float w0 = g_dinv[s0];
            float w1 = g_dinv[s1];
            float4 v0 = xl4[s0 * 16 + c];
            float4 v1 = xl4[s1 * 16 + c];
            acc.x = fmaf(v0.x, w0, acc.x); acc.y = fmaf(v0.y, w0, acc.y);
            acc.z = fmaf(v0.z, w0, acc.z); acc.w = fmaf(v0.w, w0, acc.w);
            acc.x = fmaf(v1.x, w1, acc.x); acc.y = fmaf(v1.y, w1, acc.y);
            acc.z = fmaf(v1.z, w1, acc.z); acc.w = fmaf(v1.w, w1, acc.w);
        }
        if (j < end) {
            int s0 = g_csr_src[j];
            float w0 = g_dinv[s0];
            float4 v0 = xl4[s0 * 16 + c];
            acc.x = fmaf(v0.x, w0, acc.x); acc.y = fmaf(v0.y, w0, acc.y);
            acc.z = fmaf(v0.z, w0, acc.z); acc.w = fmaf(v0.w, w0, acc.w);
        }
        float4 bb = *(const float4*)&b1[c * 4];
        hv.x = fmaxf(acc.x * di + bb.x, 0.0f);
        hv.y = fmaxf(acc.y * di + bb.y, 0.0f);
        hv.z = fmaxf(acc.z * di + bb.z, 0.0f);
        hv.w = fmaxf(acc.w * di + bb.w, 0.0f);
    }
    Hs[g * 68 + c * 4 + 0] = hv.x;
    Hs[g * 68 + c * 4 + 1] = hv.y;
    Hs[g * 68 + c * 4 + 2] = hv.z;
    Hs[g * 68 + c * 4 + 3] = hv.w;
    __syncthreads();

    int r = blockIdx.x * 16 + g;
    if (r >= n) return;
    int j = tid & 15;
    float accl = 0.0f;
#pragma unroll
    for (int k = 0; k < 64; k++) accl = fmaf(Hs[g * 68 + k], W2s[k * 16 + j], accl);
    g_l[r * 16 + j] = accl;
}

// ---------------- layer-2 gather + b2 + log_softmax (fused) ----------------
__global__ __launch_bounds__(256) void k_gather2_softmax(const float* __restrict__ b2,
                                                         float* __restrict__ out,
                                                         int n) {
    int t = blockIdx.x * 256 + threadIdx.x;
    int nd = t >> 4;
    if (nd >= n) return;
    int c = t & 15;

    int beg = g_rowstart[nd], end = g_rowstart[nd + 1];
    float di = g_dinv[nd];
    float acc = g_l[nd * 16 + c] * di;

    int j = beg;
    for (; j + 1 < end; j += 2) {
        int s0 = g_csr_src[j];
        int s1 = g_csr_src[j + 1];
        float w0 = g_dinv[s0];
        float w1 = g_dinv[s1];
        float v0 = g_l[s0 * 16 + c];
        float v1 = g_l[s1 * 16 + c];
        acc = fmaf(v0, w0, acc);
        acc = fmaf(v1, w1, acc);
    }
    if (j < end) {
        int s0 = g_csr_src[j];
        acc = fmaf(g_l[s0 * 16 + c], g_dinv[s0], acc);
    }
    acc *= di;

    float v = (c < 10) ? acc + b2[c] : -1e30f;
    float m = v;
#pragma unroll
    for (int o = 8; o > 0; o >>= 1) m = fmaxf(m, __shfl_xor_sync(0xffffffffu, m, o, 16));
    float ex = (c < 10) ? __expf(v - m) : 0.0f;
    float ssum = ex;
#pragma unroll
    for (int o = 8; o > 0; o >>= 1) ssum += __shfl_xor_sync(0xffffffffu, ssum, o, 16);
    float lse = m + __logf(ssum);
    if (c < 10) out[nd * 10 + c] = v - lse;
}

// ---------------- launcher --------------------------------------------------
extern "C" void kernel_launch(void* const* d_in, const int* in_sizes, int n_in,
                              void* d_out, int out_size) {
    const float* x   = (const float*)d_in[0];
    const void*  ei  = d_in[1];               // [2, E], int32 or int64 (detected)
    const float* W1  = (const float*)d_in[2];
    const float* b1  = (const float*)d_in[3];
    const float* W2  = (const float*)d_in[4];
    const float* b2  = (const float*)d_in[5];
    float*       out = (float*)d_out;

    const int n  = in_sizes[0] / 64;   // 50000
    const int e2 = in_sizes[1];        // 2*E elements
    const int e  = e2 / 2;             // 800000
    const int nb = (n + 255) / 256;    // 196 scan blocks (<=256 statuses)

    k_convert_hist   <<<(e2 + 255) / 256, 256>>>(ei, e2);
    k_scan           <<<nb, 256>>>(n, e);
    k_fill           <<<(e + 255) / 256, 256>>>(n, e);
    k_gemm1          <<<(n + 63) / 64, 256>>>(x, W1, n);
    k_gather1_gemm2  <<<(n * 16 + 255) / 256, 256>>>(b1, W2, n);
    k_gather2_softmax<<<(n * 16 + 255) / 256, 256>>>(b2, out, n);
}

// round 14
// speedup vs baseline: 2.3498x; 1.0044x over previous
#include <cuda_runtime.h>
#include <math.h>

// Problem constants (fixed by the dataset)
constexpr int NN = 50000;   // nodes
constexpr int EE = 800000;  // edges

// ---------------- scratch (static __device__ — no allocation) --------------
__device__ float g_dinv[NN];             // rsqrt(deg+1)
__device__ float g_xl  [NN * 64];        // x @ W1
__device__ float g_l   [NN * 16];        // relu(h) @ W2, padded 10->16
__device__ int   g_eidx[2 * EE];         // normalized int32 [src | dst]
__device__ int   g_deg [NN];             // in-degree (zero at entry; re-zeroed by k_fill)
__device__ int   g_rowstart[NN + 1];     // CSR row offsets (by dst)
__device__ int   g_cursor[NN];           // fill cursors (init = rowstart)
__device__ int   g_csr_src[EE];          // CSR adjacency: src ids grouped by dst
__device__ unsigned long long g_status[256];  // lookback scan status (flag<<32 | value)

// ---------------- packed dual-fp32 helpers (sm_103a FFMA2) ------------------
__device__ __forceinline__ void ffma2(unsigned long long& d,
                                      unsigned long long a,
                                      unsigned long long b) {
    // d = a * b + d, elementwise on packed 2xf32
    asm("fma.rn.f32x2 %0, %1, %2, %0;" : "+l"(d) : "l"(a), "l"(b));
}
__device__ __forceinline__ unsigned long long splat2(float v) {
    unsigned long long r;
    asm("mov.b64 %0, {%1, %1};" : "=l"(r) : "f"(v));
    return r;
}
__device__ __forceinline__ float2 unpack2(unsigned long long p) {
    float2 r;
    asm("mov.b64 {%0, %1}, %2;" : "=f"(r.x), "=f"(r.y) : "l"(p));
    return r;
}

// ---------------- convert to int32 + degree histogram + status reset -------
// Per-block dtype detection: sample 256 odd 32-bit words. For int64 input all
// are hi-words == 0 (ids < 50000); for int32 they are random node ids.
__global__ void k_convert_hist(const void* __restrict__ p, int e2) {
    const int tid = threadIdx.x;

    if (blockIdx.x == 0) g_status[tid] = 0ULL;  // reset scan statuses

    unsigned f = 0u;
    int nsamp = (e2 / 2 < 256) ? e2 / 2 : 256;
    if (tid < nsamp) f = ((const unsigned*)p)[2 * tid + 1];
    int is32 = __syncthreads_or(f != 0u);

    int i = blockIdx.x * 256 + tid;
    if (i >= e2) return;
    int v;
    if (is32) v = ((const int*)p)[i];
    else      v = (int)((const long long*)p)[i];
    g_eidx[i] = v;
    if (i >= e2 / 2) atomicAdd(&g_deg[v], 1);  // dst half -> degree
}

// ---------------- single-kernel exclusive scan (decoupled lookback) --------
__device__ __forceinline__ int warp_incl_scan(int v) {
    int lane = threadIdx.x & 31;
#pragma unroll
    for (int o = 1; o < 32; o <<= 1) {
        int t = __shfl_up_sync(0xffffffffu, v, o);
        if (lane >= o) v += t;
    }
    return v;
}

__global__ __launch_bounds__(256) void k_scan(int n, int e) {
    __shared__ int wsum[8];
    __shared__ int s_prefix, s_total;
    const int tid = threadIdx.x;
    const int b = blockIdx.x;
    const int i = b * 256 + tid;

    int v = (i < n) ? g_deg[i] : 0;
    if (i < n) g_dinv[i] = rsqrtf((float)(v + 1));

    int inc = warp_incl_scan(v);
    int lane = tid & 31, w = tid >> 5;
    if (lane == 31) wsum[w] = inc;
    __syncthreads();
    if (w == 0) {
        int s = (lane < 8) ? wsum[lane] : 0;
        int si = warp_incl_scan(s);
        if (lane < 8) wsum[lane] = si - s;
    }
    __syncthreads();
    inc += wsum[w];
    if (tid == 255) s_total = inc;
    __syncthreads();
    int total = s_total;

    if (tid == 0) {
        unsigned long long pack =
            ((unsigned long long)(b == 0 ? 2u : 1u) << 32) | (unsigned)total;
        atomicExch(&g_status[b], pack);
    }

    if (b == 0) {
        if (tid == 0) s_prefix = 0;
    } else if (tid < 32) {
        int prefix = 0;
        int look = b - 1;
        while (true) {
            int idx = look - tid;
            unsigned long long st;
            unsigned flag;
            do {
                st = (idx >= 0) ? *((volatile unsigned long long*)&g_status[idx])
                                : (2ULL << 32);
                flag = (unsigned)(st >> 32);
            } while (__any_sync(0xffffffffu, flag == 0u));
            int val = (int)(st & 0xffffffffULL);
            unsigned ball = __ballot_sync(0xffffffffu, flag == 2u);
            if (ball) {
                int fi = __ffs(ball) - 1;
                int contrib = (tid <= fi) ? val : 0;
#pragma unroll
                for (int o = 16; o; o >>= 1)
                    contrib += __shfl_down_sync(0xffffffffu, contrib, o);
                if (tid == 0) prefix += contrib;
                break;
            } else {
                int contrib = val;
#pragma unroll
                for (int o = 16; o; o >>= 1)
                    contrib += __shfl_down_sync(0xffffffffu, contrib, o);
                if (tid == 0) prefix += contrib;
                look -= 32;
            }
        }
        if (tid == 0) s_prefix = prefix;
    }
    __syncthreads();
    int prefix = s_prefix;

    if (b != 0 && tid == 0) {
        unsigned long long pack = (2ULL << 32) | (unsigned)(prefix + total);
        atomicExch(&g_status[b], pack);
    }

    int exc = prefix + inc - v;
    if (i < n) { g_rowstart[i] = exc; g_cursor[i] = exc; }
    if (b == 0 && tid == 0) g_rowstart[n] = e;
}

// ---------------- CSR fill (+ re-zero deg for next invocation) -------------
__global__ void k_fill(int n, int e) {
    int i = blockIdx.x * blockDim.x + threadIdx.x;
    if (i < n) g_deg[i] = 0;
    if (i >= e) return;
    int d = g_eidx[e + i];
    int pos = atomicAdd(&g_cursor[d], 1);
    g_csr_src[pos] = g_eidx[i];
}

// ---------------- GEMM1: xl = x @ W1  (n x 64) @ (64 x 64) ----------------
// Packed dual-fp32 micro-kernel: per k, 1 LDS.128 (4 a-rows) + 2 LDS.64
// (b col-pairs) + 4 splats + 8 FFMA2 = 16 FMA lanes in ~15 instrs.
__global__ __launch_bounds__(256) void k_gemm1(const float* __restrict__ x,
                                               const float* __restrict__ W,
                                               int n) {
    __shared__ float At[64 * 68];  // [k][r] transposed x tile (row = 272B, 16B-aligned)
    __shared__ float Bs[64 * 64];  // W1 [k][j]
    const int tid = threadIdx.x;
    const int row0 = blockIdx.x * 64;

    for (int i = tid; i < 4096; i += 256) Bs[i] = W[i];
    for (int i = tid; i < 4096; i += 256) {
        int r = i >> 6, k = i & 63;
        int gr = row0 + r;
        At[k * 68 + r] = (gr < n) ? x[gr * 64 + k] : 0.0f;
    }
    __syncthreads();

    const int tx = tid & 15;   // output col group (4 cols = 2 packed pairs)
    const int ty = tid >> 4;   // output row group (4 rows)

    const unsigned long long* Bs64 = (const unsigned long long*)Bs;

    unsigned long long acc[4][2];
#pragma unroll
    for (int i = 0; i < 4; i++) { acc[i][0] = 0ULL; acc[i][1] = 0ULL; }

#pragma unroll
    for (int k = 0; k < 64; k++) {
        float4 a = *(const float4*)&At[k * 68 + ty * 4];   // LDS.128
        unsigned long long b01 = Bs64[k * 32 + tx * 2];    // LDS.64 (cols 4tx,4tx+1)
        unsigned long long b23 = Bs64[k * 32 + tx * 2 + 1];// LDS.64 (cols 4tx+2,4tx+3)
        unsigned long long ax = splat2(a.x);
        unsigned long long ay = splat2(a.y);
        unsigned long long az = splat2(a.z);
        unsigned long long aw = splat2(a.w);
        ffma2(acc[0][0], ax, b01); ffma2(acc[0][1], ax, b23);
        ffma2(acc[1][0], ay, b01); ffma2(acc[1][1], ay, b23);
        ffma2(acc[2][0], az, b01); ffma2(acc[2][1], az, b23);
        ffma2(acc[3][0], aw, b01); ffma2(acc[3][1], aw, b23);
    }

#pragma unroll
    for (int i = 0; i < 4; i++) {
        int r = row0 + ty * 4 + i;
        if (r < n) {
            float2 lo = unpack2(acc[i][0]);
            float2 hi = unpack2(acc[i][1]);
            *(float4*)&g_xl[r * 64 + tx * 4] = make_float4(lo.x, lo.y, hi.x, hi.y);
        }
    }
}

// ---------------- fused: layer-1 gather + relu + b1 + GEMM2 ----------------
__global__ __launch_bounds__(256) void k_gather1_gemm2(const float* __restrict__ b1,
                                                       const float* __restrict__ W2,
                                                       int n) {
    __shared__ float Hs[16 * 68];
    __shared__ float W2s[64 * 16];
    const int tid = threadIdx.x;

    for (int i = tid; i < 64 * 16; i += 256) {
        int k = i >> 4, j = i & 15;
        W2s[i] = (j < 10) ? W2[k * 10 + j] : 0.0f;
    }

    int t = blockIdx.x * 256 + tid;
    int nd = t >> 4;
    int c = t & 15;
    int g = tid >> 4;

    float4 hv = make_float4(0.f, 0.f, 0.f, 0.f);
    if (nd < n) {
        int beg = g_rowstart[nd], end = g_rowstart[nd + 1];
        float di = g_dinv[nd];
        const float4* xl4 = (const float4*)g_xl;

        float4 a = xl4[nd * 16 + c];
        float4 acc = make_float4(a.x * di, a.y * di, a.z * di, a.w * di);

        int j = beg;
        for (; j + 1 < end; j += 2) {
            int s0 = g_csr_src[j];
            int s1 = g_csr_src[j + 1];
            float w0 = g_dinv[s0];
            float w1 = g_dinv[s1];
            float4 v0 = xl4[s0 * 16 + c];
            float4 v1 = xl4[s1 * 16 + c];
            acc.x = fmaf(v0.x, w0, acc.x); acc.y = fmaf(v0.y, w0, acc.y);
            acc.z = fmaf(v0.z, w0, acc.z); acc.w = fmaf(v0.w, w0, acc.w);
            acc.x = fmaf(v1.x, w1, acc.x); acc.y = fmaf(v1.y, w1, acc.y);
            acc.z = fmaf(v1.z, w1, acc.z); acc.w = fmaf(v1.w, w1, acc.w);
        }
        if (j < end) {
            int s0 = g_csr_src[j];
            float w0 = g_dinv[s0];
            float4 v0 = xl4[s0 * 16 + c];
            acc.x = fmaf(v0.x, w0, acc.x); acc.y = fmaf(v0.y, w0, acc.y);
            acc.z = fmaf(v0.z, w0, acc.z); acc.w = fmaf(v0.w, w0, acc.w);
        }
        float4 bb = *(const float4*)&b1[c * 4];
        hv.x = fmaxf(acc.x * di + bb.x, 0.0f);
        hv.y = fmaxf(acc.y * di + bb.y, 0.0f);
        hv.z = fmaxf(acc.z * di + bb.z, 0.0f);
        hv.w = fmaxf(acc.w * di + bb.w, 0.0f);
    }
    Hs[g * 68 + c * 4 + 0] = hv.x;
    Hs[g * 68 + c * 4 + 1] = hv.y;
    Hs[g * 68 + c * 4 + 2] = hv.z;
    Hs[g * 68 + c * 4 + 3] = hv.w;
    __syncthreads();

    int r = blockIdx.x * 16 + g;
    if (r >= n) return;
    int j = tid & 15;
    float accl = 0.0f;
#pragma unroll
    for (int k = 0; k < 64; k++) accl = fmaf(Hs[g * 68 + k], W2s[k * 16 + j], accl);
    g_l[r * 16 + j] = accl;
}

// ---------------- layer-2 gather + b2 + log_softmax (fused) ----------------
__global__ __launch_bounds__(256) void k_gather2_softmax(const float* __restrict__ b2,
                                                         float* __restrict__ out,
                                                         int n) {
    int t = blockIdx.x * 256 + threadIdx.x;
    int nd = t >> 4;
    if (nd >= n) return;
    int c = t & 15;

    int beg = g_rowstart[nd], end = g_rowstart[nd + 1];
    float di = g_dinv[nd];
    float acc = g_l[nd * 16 + c] * di;

    int j = beg;
    for (; j + 1 < end; j += 2) {
        int s0 = g_csr_src[j];
        int s1 = g_csr_src[j + 1];
        float w0 = g_dinv[s0];
        float w1 = g_dinv[s1];
        float v0 = g_l[s0 * 16 + c];
        float v1 = g_l[s1 * 16 + c];
        acc = fmaf(v0, w0, acc);
        acc = fmaf(v1, w1, acc);
    }
    if (j < end) {
        int s0 = g_csr_src[j];
        acc = fmaf(g_l[s0 * 16 + c], g_dinv[s0], acc);
    }
    acc *= di;

    float v = (c < 10) ? acc + b2[c] : -1e30f;
    float m = v;
#pragma unroll
    for (int o = 8; o > 0; o >>= 1) m = fmaxf(m, __shfl_xor_sync(0xffffffffu, m, o, 16));
    float ex = (c < 10) ? __expf(v - m) : 0.0f;
    float ssum = ex;
#pragma unroll
    for (int o = 8; o > 0; o >>= 1) ssum += __shfl_xor_sync(0xffffffffu, ssum, o, 16);
    float lse = m + __logf(ssum);
    if (c < 10) out[nd * 10 + c] = v - lse;
}

// ---------------- launcher --------------------------------------------------
extern "C" void kernel_launch(void* const* d_in, const int* in_sizes, int n_in,
                              void* d_out, int out_size) {
    const float* x   = (const float*)d_in[0];
    const void*  ei  = d_in[1];               // [2, E], int32 or int64 (detected)
    const float* W1  = (const float*)d_in[2];
    const float* b1  = (const float*)d_in[3];
    const float* W2  = (const float*)d_in[4];
    const float* b2  = (const float*)d_in[5];
    float*       out = (float*)d_out;

    const int n  = in_sizes[0] / 64;   // 50000
    const int e2 = in_sizes[1];        // 2*E elements
    const int e  = e2 / 2;             // 800000
    const int nb = (n + 255) / 256;    // 196 scan blocks (<=256 statuses)

    k_convert_hist   <<<(e2 + 255) / 256, 256>>>(ei, e2);
    k_scan           <<<nb, 256>>>(n, e);
    k_fill           <<<(e + 255) / 256, 256>>>(n, e);
    k_gemm1          <<<(n + 63) / 64, 256>>>(x, W1, n);
    k_gather1_gemm2  <<<(n * 16 + 255) / 256, 256>>>(b1, W2, n);
    k_gather2_softmax<<<(n * 16 + 255) / 256, 256>>>(b2, out, n);
}

// round 15
// speedup vs baseline: 2.5610x; 1.0899x over previous
#include <cuda_runtime.h>
#include <math.h>

// Problem constants (fixed by the dataset)
constexpr int NN = 50000;   // nodes
constexpr int EE = 800000;  // edges

// ---------------- scratch (static __device__ — no allocation) --------------
__device__ float g_dinv[NN];             // rsqrt(deg+1)
__device__ float g_xl  [NN * 64];        // x @ W1
__device__ float g_l   [NN * 16];        // relu(h) @ W2, padded 10->16
__device__ int   g_eidx[2 * EE];         // normalized int32 [src | dst]
__device__ int   g_deg [NN];             // in-degree (zero at entry; re-zeroed by k_fill)
__device__ int   g_rowstart[NN + 1];     // CSR row offsets (by dst)
__device__ int   g_cursor[NN];           // fill cursors (init = rowstart)
__device__ int   g_csr_src[EE];          // CSR adjacency: src ids grouped by dst
__device__ unsigned long long g_status[256];  // lookback scan status (flag<<32 | value)

// ---------------- packed dual-fp32 helpers (sm_103a FFMA2) ------------------
__device__ __forceinline__ void ffma2(unsigned long long& d,
                                      unsigned long long a,
                                      unsigned long long b) {
    asm("fma.rn.f32x2 %0, %1, %2, %0;" : "+l"(d) : "l"(a), "l"(b));
}
__device__ __forceinline__ unsigned long long splat2(float v) {
    unsigned long long r;
    asm("mov.b64 %0, {%1, %1};" : "=l"(r) : "f"(v));
    return r;
}
__device__ __forceinline__ float2 unpack2(unsigned long long p) {
    float2 r;
    asm("mov.b64 {%0, %1}, %2;" : "=f"(r.x), "=f"(r.y) : "l"(p));
    return r;
}

// ---------------- K1: fused [gemm1 | convert+hist] (independent work) -------
// Blocks [0, gemm_blocks): xl = x @ W1 (64-row tiles, packed FFMA2 kernel).
// Blocks [gemm_blocks, ...): edge-index convert + degree histogram + status
// reset. The two halves touch disjoint data and have no ordering requirement.
__global__ __launch_bounds__(256) void k_gemm1_convert(const float* __restrict__ x,
                                                       const float* __restrict__ W,
                                                       const void* __restrict__ p,
                                                       int n, int e2, int gemm_blocks) {
    __shared__ float At[64 * 68];  // [k][r] transposed x tile
    __shared__ float Bs[64 * 64];  // W1 [k][j]
    const int tid = threadIdx.x;

    if (blockIdx.x >= gemm_blocks) {
        // ---- convert + hist half ----
        const int cb = blockIdx.x - gemm_blocks;
        if (cb == 0) g_status[tid] = 0ULL;  // reset scan statuses

        unsigned f = 0u;
        int nsamp = (e2 / 2 < 256) ? e2 / 2 : 256;
        if (tid < nsamp) f = ((const unsigned*)p)[2 * tid + 1];
        int is32 = __syncthreads_or(f != 0u);

        int i = cb * 256 + tid;
        if (i >= e2) return;
        int v;
        if (is32) v = ((const int*)p)[i];
        else      v = (int)((const long long*)p)[i];
        g_eidx[i] = v;
        if (i >= e2 / 2) atomicAdd(&g_deg[v], 1);  // dst half -> degree
        return;
    }

    // ---- GEMM half ----
    const int row0 = blockIdx.x * 64;

    for (int i = tid; i < 4096; i += 256) Bs[i] = W[i];
    for (int i = tid; i < 4096; i += 256) {
        int r = i >> 6, k = i & 63;
        int gr = row0 + r;
        At[k * 68 + r] = (gr < n) ? x[gr * 64 + k] : 0.0f;
    }
    __syncthreads();

    const int tx = tid & 15;
    const int ty = tid >> 4;
    const unsigned long long* Bs64 = (const unsigned long long*)Bs;

    unsigned long long acc[4][2];
#pragma unroll
    for (int i = 0; i < 4; i++) { acc[i][0] = 0ULL; acc[i][1] = 0ULL; }

#pragma unroll
    for (int k = 0; k < 64; k++) {
        float4 a = *(const float4*)&At[k * 68 + ty * 4];
        unsigned long long b01 = Bs64[k * 32 + tx * 2];
        unsigned long long b23 = Bs64[k * 32 + tx * 2 + 1];
        unsigned long long ax = splat2(a.x);
        unsigned long long ay = splat2(a.y);
        unsigned long long az = splat2(a.z);
        unsigned long long aw = splat2(a.w);
        ffma2(acc[0][0], ax, b01); ffma2(acc[0][1], ax, b23);
        ffma2(acc[1][0], ay, b01); ffma2(acc[1][1], ay, b23);
        ffma2(acc[2][0], az, b01); ffma2(acc[2][1], az, b23);
        ffma2(acc[3][0], aw, b01); ffma2(acc[3][1], aw, b23);
    }

#pragma unroll
    for (int i = 0; i < 4; i++) {
        int r = row0 + ty * 4 + i;
        if (r < n) {
            float2 lo = unpack2(acc[i][0]);
            float2 hi = unpack2(acc[i][1]);
            *(float4*)&g_xl[r * 64 + tx * 4] = make_float4(lo.x, lo.y, hi.x, hi.y);
        }
    }
}

// ---------------- single-kernel exclusive scan (decoupled lookback) --------
__device__ __forceinline__ int warp_incl_scan(int v) {
    int lane = threadIdx.x & 31;
#pragma unroll
    for (int o = 1; o < 32; o <<= 1) {
        int t = __shfl_up_sync(0xffffffffu, v, o);
        if (lane >= o) v += t;
    }
    return v;
}

__global__ __launch_bounds__(256) void k_scan(int n, int e) {
    __shared__ int wsum[8];
    __shared__ int s_prefix, s_total;
    const int tid = threadIdx.x;
    const int b = blockIdx.x;
    const int i = b * 256 + tid;

    int v = (i < n) ? g_deg[i] : 0;
    if (i < n) g_dinv[i] = rsqrtf((float)(v + 1));

    int inc = warp_incl_scan(v);
    int lane = tid & 31, w = tid >> 5;
    if (lane == 31) wsum[w] = inc;
    __syncthreads();
    if (w == 0) {
        int s = (lane < 8) ? wsum[lane] : 0;
        int si = warp_incl_scan(s);
        if (lane < 8) wsum[lane] = si - s;
    }
    __syncthreads();
    inc += wsum[w];
    if (tid == 255) s_total = inc;
    __syncthreads();
    int total = s_total;

    if (tid == 0) {
        unsigned long long pack =
            ((unsigned long long)(b == 0 ? 2u : 1u) << 32) | (unsigned)total;
        atomicExch(&g_status[b], pack);
    }

    if (b == 0) {
        if (tid == 0) s_prefix = 0;
    } else if (tid < 32) {
        int prefix = 0;
        int look = b - 1;
        while (true) {
            int idx = look - tid;
            unsigned long long st;
            unsigned flag;
            do {
                st = (idx >= 0) ? *((volatile unsigned long long*)&g_status[idx])
                                : (2ULL << 32);
                flag = (unsigned)(st >> 32);
            } while (__any_sync(0xffffffffu, flag == 0u));
            int val = (int)(st & 0xffffffffULL);
            unsigned ball = __ballot_sync(0xffffffffu, flag == 2u);
            if (ball) {
                int fi = __ffs(ball) - 1;
                int contrib = (tid <= fi) ? val : 0;
#pragma unroll
                for (int o = 16; o; o >>= 1)
                    contrib += __shfl_down_sync(0xffffffffu, contrib, o);
                if (tid == 0) prefix += contrib;
                break;
            } else {
                int contrib = val;
#pragma unroll
                for (int o = 16; o; o >>= 1)
                    contrib += __shfl_down_sync(0xffffffffu, contrib, o);
                if (tid == 0) prefix += contrib;
                look -= 32;
            }
        }
        if (tid == 0) s_prefix = prefix;
    }
    __syncthreads();
    int prefix = s_prefix;

    if (b != 0 && tid == 0) {
        unsigned long long pack = (2ULL << 32) | (unsigned)(prefix + total);
        atomicExch(&g_status[b], pack);
    }

    int exc = prefix + inc - v;
    if (i < n) { g_rowstart[i] = exc; g_cursor[i] = exc; }
    if (b == 0 && tid == 0) g_rowstart[n] = e;
}

// ---------------- CSR fill (+ re-zero deg for next invocation) -------------
__global__ void k_fill(int n, int e) {
    int i = blockIdx.x * blockDim.x + threadIdx.x;
    if (i < n) g_deg[i] = 0;
    if (i >= e) return;
    int d = g_eidx[e + i];
    int pos = atomicAdd(&g_cursor[d], 1);
    g_csr_src[pos] = g_eidx[i];
}

// ---------------- fused: layer-1 gather + relu + b1 + GEMM2 ----------------
// 16 threads/node, float4/lane gather, 4-deep unroll for MLP.
__global__ __launch_bounds__(256) void k_gather1_gemm2(const float* __restrict__ b1,
                                                       const float* __restrict__ W2,
                                                       int n) {
    __shared__ float Hs[16 * 68];
    __shared__ float W2s[64 * 16];
    const int tid = threadIdx.x;

    for (int i = tid; i < 64 * 16; i += 256) {
        int k = i >> 4, j = i & 15;
        W2s[i] = (j < 10) ? W2[k * 10 + j] : 0.0f;
    }

    int t = blockIdx.x * 256 + tid;
    int nd = t >> 4;
    int c = t & 15;
    int g = tid >> 4;

    float4 hv = make_float4(0.f, 0.f, 0.f, 0.f);
    if (nd < n) {
        int beg = g_rowstart[nd], end = g_rowstart[nd + 1];
        float di = g_dinv[nd];
        const float4* xl4 = (const float4*)g_xl;

        float4 a = xl4[nd * 16 + c];
        float4 acc = make_float4(a.x * di, a.y * di, a.z * di, a.w * di);

        int j = beg;
        for (; j + 3 < end; j += 4) {
            int s0 = g_csr_src[j];
            int s1 = g_csr_src[j + 1];
            int s2 = g_csr_src[j + 2];
            int s3 = g_csr_src[j + 3];
            float w0 = g_dinv[s0], w1 = g_dinv[s1];
            float w2 = g_dinv[s2], w3 = g_dinv[s3];
            float4 v0 = xl4[s0 * 16 + c];
            float4 v1 = xl4[s1 * 16 + c];
            float4 v2 = xl4[s2 * 16 + c];
            float4 v3 = xl4[s3 * 16 + c];
            acc.x = fmaf(v0.x, w0, acc.x); acc.y = fmaf(v0.y, w0, acc.y);
            acc.z = fmaf(v0.z, w0, acc.z); acc.w = fmaf(v0.w, w0, acc.w);
            acc.x = fmaf(v1.x, w1, acc.x); acc.y = fmaf(v1.y, w1, acc.y);
            acc.z = fmaf(v1.z, w1, acc.z); acc.w = fmaf(v1.w, w1, acc.w);
            acc.x = fmaf(v2.x, w2, acc.x); acc.y = fmaf(v2.y, w2, acc.y);
            acc.z = fmaf(v2.z, w2, acc.z); acc.w = fmaf(v2.w, w2, acc.w);
            acc.x = fmaf(v3.x, w3, acc.x); acc.y = fmaf(v3.y, w3, acc.y);
            acc.z = fmaf(v3.z, w3, acc.z); acc.w = fmaf(v3.w, w3, acc.w);
        }
        for (; j < end; ++j) {
            int s0 = g_csr_src[j];
            float w0 = g_dinv[s0];
            float4 v0 = xl4[s0 * 16 + c];
            acc.x = fmaf(v0.x, w0, acc.x); acc.y = fmaf(v0.y, w0, acc.y);
            acc.z = fmaf(v0.z, w0, acc.z); acc.w = fmaf(v0.w, w0, acc.w);
        }
        float4 bb = *(const float4*)&b1[c * 4];
        hv.x = fmaxf(acc.x * di + bb.x, 0.0f);
        hv.y = fmaxf(acc.y * di + bb.y, 0.0f);
        hv.z = fmaxf(acc.z * di + bb.z, 0.0f);
        hv.w = fmaxf(acc.w * di + bb.w, 0.0f);
    }
    Hs[g * 68 + c * 4 + 0] = hv.x;
    Hs[g * 68 + c * 4 + 1] = hv.y;
    Hs[g * 68 + c * 4 + 2] = hv.z;
    Hs[g * 68 + c * 4 + 3] = hv.w;
    __syncthreads();

    int r = blockIdx.x * 16 + g;
    if (r >= n) return;
    int j = tid & 15;
    float accl = 0.0f;
#pragma unroll
    for (int k = 0; k < 64; k++) accl = fmaf(Hs[g * 68 + k], W2s[k * 16 + j], accl);
    g_l[r * 16 + j] = accl;
}

// ---------------- layer-2 gather + b2 + log_softmax (fused) ----------------
__global__ __launch_bounds__(256) void k_gather2_softmax(const float* __restrict__ b2,
                                                         float* __restrict__ out,
                                                         int n) {
    int t = blockIdx.x * 256 + threadIdx.x;
    int nd = t >> 4;
    if (nd >= n) return;
    int c = t & 15;

    int beg = g_rowstart[nd], end = g_rowstart[nd + 1];
    float di = g_dinv[nd];
    float acc = g_l[nd * 16 + c] * di;

    int j = beg;
    for (; j + 3 < end; j += 4) {
        int s0 = g_csr_src[j];
        int s1 = g_csr_src[j + 1];
        int s2 = g_csr_src[j + 2];
        int s3 = g_csr_src[j + 3];
        float w0 = g_dinv[s0], w1 = g_dinv[s1];
        float w2 = g_dinv[s2], w3 = g_dinv[s3];
        float v0 = g_l[s0 * 16 + c];
        float v1 = g_l[s1 * 16 + c];
        float v2 = g_l[s2 * 16 + c];
        float v3 = g_l[s3 * 16 + c];
        acc = fmaf(v0, w0, acc);
        acc = fmaf(v1, w1, acc);
        acc = fmaf(v2, w2, acc);
        acc = fmaf(v3, w3, acc);
    }
    for (; j < end; ++j) {
        int s0 = g_csr_src[j];
        acc = fmaf(g_l[s0 * 16 + c], g_dinv[s0], acc);
    }
    acc *= di;

    float v = (c < 10) ? acc + b2[c] : -1e30f;
    float m = v;
#pragma unroll
    for (int o = 8; o > 0; o >>= 1) m = fmaxf(m, __shfl_xor_sync(0xffffffffu, m, o, 16));
    float ex = (c < 10) ? __expf(v - m) : 0.0f;
    float ssum = ex;
#pragma unroll
    for (int o = 8; o > 0; o >>= 1) ssum += __shfl_xor_sync(0xffffffffu, ssum, o, 16);
    float lse = m + __logf(ssum);
    if (c < 10) out[nd * 10 + c] = v - lse;
}

// ---------------- launcher --------------------------------------------------
extern "C" void kernel_launch(void* const* d_in, const int* in_sizes, int n_in,
                              void* d_out, int out_size) {
    const float* x   = (const float*)d_in[0];
    const void*  ei  = d_in[1];               // [2, E], int32 or int64 (detected)
    const float* W1  = (const float*)d_in[2];
    const float* b1  = (const float*)d_in[3];
    const float* W2  = (const float*)d_in[4];
    const float* b2  = (const float*)d_in[5];
    float*       out = (float*)d_out;

    const int n  = in_sizes[0] / 64;   // 50000
    const int e2 = in_sizes[1];        // 2*E elements
    const int e  = e2 / 2;             // 800000
    const int nb = (n + 255) / 256;    // 196 scan blocks (<=256 statuses)

    const int gemm_blocks = (n + 63) / 64;       // 782
    const int conv_blocks = (e2 + 255) / 256;    // 6250

    k_gemm1_convert  <<<gemm_blocks + conv_blocks, 256>>>(x, W1, ei, n, e2, gemm_blocks);
    k_scan           <<<nb, 256>>>(n, e);
    k_fill           <<<(e + 255) / 256, 256>>>(n, e);
    k_gather1_gemm2  <<<(n * 16 + 255) / 256, 256>>>(b1, W2, n);
    k_gather2_softmax<<<(n * 16 + 255) / 256, 256>>>(b2, out, n);
}

// round 16
// speedup vs baseline: 2.6211x; 1.0235x over previous
#include <cuda_runtime.h>
#include <math.h>

// Problem constants (fixed by the dataset)
constexpr int NN = 50000;   // nodes
constexpr int EE = 800000;  // edges

// ---------------- scratch (static __device__ — no allocation) --------------
__device__ float g_dinv[NN];             // rsqrt(deg+1)
__device__ float g_xl  [NN * 64];        // dinv * (x @ W1)   (scaled in k_fill)
__device__ float g_l   [NN * 16];        // dinv * (relu(h) @ W2), padded 10->16
__device__ int   g_eidx[2 * EE];         // normalized int32 [src | dst]
__device__ int   g_deg [NN];             // in-degree (zero at entry; re-zeroed by k_fill)
__device__ int   g_rowstart[NN + 1];     // CSR row offsets (by dst)
__device__ int   g_cursor[NN];           // fill cursors (init = rowstart)
__device__ int   g_csr_src[EE];          // CSR adjacency: src ids grouped by dst
__device__ unsigned long long g_status[256];  // lookback scan status (flag<<32 | value)

// ---------------- packed dual-fp32 helpers (sm_103a FFMA2) ------------------
__device__ __forceinline__ void ffma2(unsigned long long& d,
                                      unsigned long long a,
                                      unsigned long long b) {
    asm("fma.rn.f32x2 %0, %1, %2, %0;" : "+l"(d) : "l"(a), "l"(b));
}
__device__ __forceinline__ unsigned long long splat2(float v) {
    unsigned long long r;
    asm("mov.b64 %0, {%1, %1};" : "=l"(r) : "f"(v));
    return r;
}
__device__ __forceinline__ float2 unpack2(unsigned long long p) {
    float2 r;
    asm("mov.b64 {%0, %1}, %2;" : "=f"(r.x), "=f"(r.y) : "l"(p));
    return r;
}

// ---------------- K1: fused [gemm1 | convert+hist] (independent work) -------
__global__ __launch_bounds__(256) void k_gemm1_convert(const float* __restrict__ x,
                                                       const float* __restrict__ W,
                                                       const void* __restrict__ p,
                                                       int n, int e2, int gemm_blocks) {
    __shared__ float At[64 * 68];  // [k][r] transposed x tile
    __shared__ float Bs[64 * 64];  // W1 [k][j]
    const int tid = threadIdx.x;

    if (blockIdx.x >= gemm_blocks) {
        // ---- convert + hist half ----
        const int cb = blockIdx.x - gemm_blocks;
        if (cb == 0) g_status[tid] = 0ULL;  // reset scan statuses

        unsigned f = 0u;
        int nsamp = (e2 / 2 < 256) ? e2 / 2 : 256;
        if (tid < nsamp) f = ((const unsigned*)p)[2 * tid + 1];
        int is32 = __syncthreads_or(f != 0u);

        int i = cb * 256 + tid;
        if (i >= e2) return;
        int v;
        if (is32) v = ((const int*)p)[i];
        else      v = (int)((const long long*)p)[i];
        g_eidx[i] = v;
        if (i >= e2 / 2) atomicAdd(&g_deg[v], 1);  // dst half -> degree
        return;
    }

    // ---- GEMM half ----
    const int row0 = blockIdx.x * 64;

    for (int i = tid; i < 4096; i += 256) Bs[i] = W[i];
    for (int i = tid; i < 4096; i += 256) {
        int r = i >> 6, k = i & 63;
        int gr = row0 + r;
        At[k * 68 + r] = (gr < n) ? x[gr * 64 + k] : 0.0f;
    }
    __syncthreads();

    const int tx = tid & 15;
    const int ty = tid >> 4;
    const unsigned long long* Bs64 = (const unsigned long long*)Bs;

    unsigned long long acc[4][2];
#pragma unroll
    for (int i = 0; i < 4; i++) { acc[i][0] = 0ULL; acc[i][1] = 0ULL; }

#pragma unroll
    for (int k = 0; k < 64; k++) {
        float4 a = *(const float4*)&At[k * 68 + ty * 4];
        unsigned long long b01 = Bs64[k * 32 + tx * 2];
        unsigned long long b23 = Bs64[k * 32 + tx * 2 + 1];
        unsigned long long ax = splat2(a.x);
        unsigned long long ay = splat2(a.y);
        unsigned long long az = splat2(a.z);
        unsigned long long aw = splat2(a.w);
        ffma2(acc[0][0], ax, b01); ffma2(acc[0][1], ax, b23);
        ffma2(acc[1][0], ay, b01); ffma2(acc[1][1], ay, b23);
        ffma2(acc[2][0], az, b01); ffma2(acc[2][1], az, b23);
        ffma2(acc[3][0], aw, b01); ffma2(acc[3][1], aw, b23);
    }

#pragma unroll
    for (int i = 0; i < 4; i++) {
        int r = row0 + ty * 4 + i;
        if (r < n) {
            float2 lo = unpack2(acc[i][0]);
            float2 hi = unpack2(acc[i][1]);
            *(float4*)&g_xl[r * 64 + tx * 4] = make_float4(lo.x, lo.y, hi.x, hi.y);
        }
    }
}

// ---------------- single-kernel exclusive scan (decoupled lookback) --------
__device__ __forceinline__ int warp_incl_scan(int v) {
    int lane = threadIdx.x & 31;
#pragma unroll
    for (int o = 1; o < 32; o <<= 1) {
        int t = __shfl_up_sync(0xffffffffu, v, o);
        if (lane >= o) v += t;
    }
    return v;
}

__global__ __launch_bounds__(256) void k_scan(int n, int e) {
    __shared__ int wsum[8];
    __shared__ int s_prefix, s_total;
    const int tid = threadIdx.x;
    const int b = blockIdx.x;
    const int i = b * 256 + tid;

    int v = (i < n) ? g_deg[i] : 0;
    if (i < n) g_dinv[i] = rsqrtf((float)(v + 1));

    int inc = warp_incl_scan(v);
    int lane = tid & 31, w = tid >> 5;
    if (lane == 31) wsum[w] = inc;
    __syncthreads();
    if (w == 0) {
        int s = (lane < 8) ? wsum[lane] : 0;
        int si = warp_incl_scan(s);
        if (lane < 8) wsum[lane] = si - s;
    }
    __syncthreads();
    inc += wsum[w];
    if (tid == 255) s_total = inc;
    __syncthreads();
    int total = s_total;

    if (tid == 0) {
        unsigned long long pack =
            ((unsigned long long)(b == 0 ? 2u : 1u) << 32) | (unsigned)total;
        atomicExch(&g_status[b], pack);
    }

    if (b == 0) {
        if (tid == 0) s_prefix = 0;
    } else if (tid < 32) {
        int prefix = 0;
        int look = b - 1;
        while (true) {
            int idx = look - tid;
            unsigned long long st;
            unsigned flag;
            do {
                st = (idx >= 0) ? *((volatile unsigned long long*)&g_status[idx])
                                : (2ULL << 32);
                flag = (unsigned)(st >> 32);
            } while (__any_sync(0xffffffffu, flag == 0u));
            int val = (int)(st & 0xffffffffULL);
            unsigned ball = __ballot_sync(0xffffffffu, flag == 2u);
            if (ball) {
                int fi = __ffs(ball) - 1;
                int contrib = (tid <= fi) ? val : 0;
#pragma unroll
                for (int o = 16; o; o >>= 1)
                    contrib += __shfl_down_sync(0xffffffffu, contrib, o);
                if (tid == 0) prefix += contrib;
                break;
            } else {
                int contrib = val;
#pragma unroll
                for (int o = 16; o; o >>= 1)
                    contrib += __shfl_down_sync(0xffffffffu, contrib, o);
                if (tid == 0) prefix += contrib;
                look -= 32;
            }
        }
        if (tid == 0) s_prefix = prefix;
    }
    __syncthreads();
    int prefix = s_prefix;

    if (b != 0 && tid == 0) {
        unsigned long long pack = (2ULL << 32) | (unsigned)(prefix + total);
        atomicExch(&g_status[b], pack);
    }

    int exc = prefix + inc - v;
    if (i < n) { g_rowstart[i] = exc; g_cursor[i] = exc; }
    if (b == 0 && tid == 0) g_rowstart[n] = e;
}

// ---------------- CSR fill + xl pre-scale (+ re-zero deg) ------------------
// Thread i (< e = n*16) also scales one float4 of g_xl by dinv[node]:
// xls[v] = dinv[v] * xl[v]  -> gathers need no per-neighbor weights.
__global__ void k_fill(int n, int e) {
    int i = blockIdx.x * blockDim.x + threadIdx.x;
    if (i < n) g_deg[i] = 0;
    if (i >= e) return;

    // CSR fill
    int d = g_eidx[e + i];
    int pos = atomicAdd(&g_cursor[d], 1);
    g_csr_src[pos] = g_eidx[i];

    // pre-scale xl (e == n*16 float4s exactly for this dataset; guard anyway)
    if (i < n * 16) {
        float w = g_dinv[i >> 4];
        float4* p4 = (float4*)g_xl + i;
        float4 v = *p4;
        v.x *= w; v.y *= w; v.z *= w; v.w *= w;
        *p4 = v;
    }
}

// ---------------- fused: layer-1 gather + relu + b1 + GEMM2 ----------------
// xls rows are pre-scaled: acc = xls[d] + sum xls[s]; h = relu(acc*di + b1).
// Phase 2 writes g_l scaled by dinv[r] so gather2 also needs no weights.
__global__ __launch_bounds__(256) void k_gather1_gemm2(const float* __restrict__ b1,
                                                       const float* __restrict__ W2,
                                                       int n) {
    __shared__ float Hs[16 * 68];
    __shared__ float W2s[64 * 16];
    const int tid = threadIdx.x;

    for (int i = tid; i < 64 * 16; i += 256) {
        int k = i >> 4, j = i & 15;
        W2s[i] = (j < 10) ? W2[k * 10 + j] : 0.0f;
    }

    int t = blockIdx.x * 256 + tid;
    int nd = t >> 4;
    int c = t & 15;
    int g = tid >> 4;

    float4 hv = make_float4(0.f, 0.f, 0.f, 0.f);
    if (nd < n) {
        int beg = g_rowstart[nd], end = g_rowstart[nd + 1];
        float di = g_dinv[nd];
        const float4* xl4 = (const float4*)g_xl;

        float4 acc = xl4[nd * 16 + c];   // self term (already dinv-scaled)

        int j = beg;
        for (; j + 3 < end; j += 4) {
            int s0 = g_csr_src[j];
            int s1 = g_csr_src[j + 1];
            int s2 = g_csr_src[j + 2];
            int s3 = g_csr_src[j + 3];
            float4 v0 = xl4[s0 * 16 + c];
            float4 v1 = xl4[s1 * 16 + c];
            float4 v2 = xl4[s2 * 16 + c];
            float4 v3 = xl4[s3 * 16 + c];
            acc.x += v0.x + v1.x; acc.y += v0.y + v1.y;
            acc.z += v0.z + v1.z; acc.w += v0.w + v1.w;
            acc.x += v2.x + v3.x; acc.y += v2.y + v3.y;
            acc.z += v2.z + v3.z; acc.w += v2.w + v3.w;
        }
        for (; j < end; ++j) {
            int s0 = g_csr_src[j];
            float4 v0 = xl4[s0 * 16 + c];
            acc.x += v0.x; acc.y += v0.y; acc.z += v0.z; acc.w += v0.w;
        }
        float4 bb = *(const float4*)&b1[c * 4];
        hv.x = fmaxf(fmaf(acc.x, di, bb.x), 0.0f);
        hv.y = fmaxf(fmaf(acc.y, di, bb.y), 0.0f);
        hv.z = fmaxf(fmaf(acc.z, di, bb.z), 0.0f);
        hv.w = fmaxf(fmaf(acc.w, di, bb.w), 0.0f);
    }
    Hs[g * 68 + c * 4 + 0] = hv.x;
    Hs[g * 68 + c * 4 + 1] = hv.y;
    Hs[g * 68 + c * 4 + 2] = hv.z;
    Hs[g * 68 + c * 4 + 3] = hv.w;
    __syncthreads();

    int r = blockIdx.x * 16 + g;
    if (r >= n) return;
    int j = tid & 15;
    float accl = 0.0f;
#pragma unroll
    for (int k = 0; k < 64; k++) accl = fmaf(Hs[g * 68 + k], W2s[k * 16 + j], accl);
    g_l[r * 16 + j] = accl * g_dinv[r];   // pre-scale for gather2
}

// ---------------- layer-2 gather + b2 + log_softmax (fused) ----------------
__global__ __launch_bounds__(256) void k_gather2_softmax(const float* __restrict__ b2,
                                                         float* __restrict__ out,
                                                         int n) {
    int t = blockIdx.x * 256 + threadIdx.x;
    int nd = t >> 4;
    if (nd >= n) return;
    int c = t & 15;

    int beg = g_rowstart[nd], end = g_rowstart[nd + 1];
    float di = g_dinv[nd];
    float acc = g_l[nd * 16 + c];   // self term (already dinv-scaled)

    int j = beg;
    for (; j + 3 < end; j += 4) {
        int s0 = g_csr_src[j];
        int s1 = g_csr_src[j + 1];
        int s2 = g_csr_src[j + 2];
        int s3 = g_csr_src[j + 3];
        float v0 = g_l[s0 * 16 + c];
        float v1 = g_l[s1 * 16 + c];
        float v2 = g_l[s2 * 16 + c];
        float v3 = g_l[s3 * 16 + c];
        acc += (v0 + v1) + (v2 + v3);
    }
    for (; j < end; ++j) acc += g_l[g_csr_src[j] * 16 + c];
    acc *= di;

    float v = (c < 10) ? acc + b2[c] : -1e30f;
    float m = v;
#pragma unroll
    for (int o = 8; o > 0; o >>= 1) m = fmaxf(m, __shfl_xor_sync(0xffffffffu, m, o, 16));
    float ex = (c < 10) ? __expf(v - m) : 0.0f;
    float ssum = ex;
#pragma unroll
    for (int o = 8; o > 0; o >>= 1) ssum += __shfl_xor_sync(0xffffffffu, ssum, o, 16);
    float lse = m + __logf(ssum);
    if (c < 10) out[nd * 10 + c] = v - lse;
}

// ---------------- launcher --------------------------------------------------
extern "C" void kernel_launch(void* const* d_in, const int* in_sizes, int n_in,
                              void* d_out, int out_size) {
    const float* x   = (const float*)d_in[0];
    const void*  ei  = d_in[1];               // [2, E], int32 or int64 (detected)
    const float* W1  = (const float*)d_in[2];
    const float* b1  = (const float*)d_in[3];
    const float* W2  = (const float*)d_in[4];
    const float* b2  = (const float*)d_in[5];
    float*       out = (float*)d_out;

    const int n  = in_sizes[0] / 64;   // 50000
    const int e2 = in_sizes[1];        // 2*E elements
    const int e  = e2 / 2;             // 800000
    const int nb = (n + 255) / 256;    // 196 scan blocks (<=256 statuses)

    const int gemm_blocks = (n + 63) / 64;       // 782
    const int conv_blocks = (e2 + 255) / 256;    // 6250
    // k_fill must cover max(e, n*16) threads
    const long long fill_threads = (long long)e > (long long)n * 16 ? e : (long long)n * 16;

    k_gemm1_convert  <<<gemm_blocks + conv_blocks, 256>>>(x, W1, ei, n, e2, gemm_blocks);
    k_scan           <<<nb, 256>>>(n, e);
    k_fill           <<<(int)((fill_threads + 255) / 256), 256>>>(n, e);
    k_gather1_gemm2  <<<(n * 16 + 255) / 256, 256>>>(b1, W2, n);
    k_gather2_softmax<<<(n * 16 + 255) / 256, 256>>>(b2, out, n);
}

// round 17
// speedup vs baseline: 2.7722x; 1.0576x over previous
#include <cuda_runtime.h>
#include <cuda_fp16.h>
#include <math.h>

// Problem constants (fixed by the dataset)
constexpr int NN = 50000;   // nodes
constexpr int EE = 800000;  // edges

// ---------------- scratch (static __device__ — no allocation) --------------
__device__ float  g_dinv[NN];            // rsqrt(deg+1)
__device__ __half g_xlh[NN * 64];        // fp16 dinv*(x@W1), 128B rows
__device__ float  g_l  [NN * 16];        // dinv*(relu(h)@W2), padded 10->16
__device__ int    g_eidx[2 * EE];        // normalized int32 [src | dst]
__device__ int    g_deg [NN];            // in-degree (zero at entry; re-zeroed by k_fill)
__device__ int    g_rowstart[NN + 1];    // CSR row offsets (by dst)
__device__ int    g_cursor[NN];          // fill cursors (init = rowstart)
__device__ int    g_csr_src[EE];         // CSR adjacency: src ids grouped by dst
__device__ unsigned long long g_status[256];  // lookback scan status

// ---------------- packed dual-fp32 helpers (sm_103a FFMA2) ------------------
__device__ __forceinline__ void ffma2(unsigned long long& d,
                                      unsigned long long a,
                                      unsigned long long b) {
    asm("fma.rn.f32x2 %0, %1, %2, %0;" : "+l"(d) : "l"(a), "l"(b));
}
__device__ __forceinline__ unsigned long long splat2(float v) {
    unsigned long long r;
    asm("mov.b64 %0, {%1, %1};" : "=l"(r) : "f"(v));
    return r;
}
__device__ __forceinline__ float2 unpack2(unsigned long long p) {
    float2 r;
    asm("mov.b64 {%0, %1}, %2;" : "=f"(r.x), "=f"(r.y) : "l"(p));
    return r;
}
// 4 packed halves (uint2) -> float4
__device__ __forceinline__ float4 h4_to_f4(uint2 u) {
    __half2 a = *(__half2*)&u.x;
    __half2 b = *(__half2*)&u.y;
    float2 fa = __half22float2(a);
    float2 fb = __half22float2(b);
    return make_float4(fa.x, fa.y, fb.x, fb.y);
}

// ---------------- K1: fused [gemm1 | convert+hist] (independent work) -------
__global__ __launch_bounds__(256) void k_gemm1_convert(const float* __restrict__ x,
                                                       const float* __restrict__ W,
                                                       const void* __restrict__ p,
                                                       int n, int e2, int gemm_blocks) {
    __shared__ float At[64 * 68];  // [k][r] transposed x tile
    __shared__ float Bs[64 * 64];  // W1 [k][j]
    const int tid = threadIdx.x;

    if (blockIdx.x >= gemm_blocks) {
        // ---- convert + hist half ----
        const int cb = blockIdx.x - gemm_blocks;
        if (cb == 0) g_status[tid] = 0ULL;  // reset scan statuses

        unsigned f = 0u;
        int nsamp = (e2 / 2 < 256) ? e2 / 2 : 256;
        if (tid < nsamp) f = ((const unsigned*)p)[2 * tid + 1];
        int is32 = __syncthreads_or(f != 0u);

        int i = cb * 256 + tid;
        if (i >= e2) return;
        int v;
        if (is32) v = ((const int*)p)[i];
        else      v = (int)((const long long*)p)[i];
        g_eidx[i] = v;
        if (i >= e2 / 2) atomicAdd(&g_deg[v], 1);  // dst half -> degree
        return;
    }

    // ---- GEMM half ----
    const int row0 = blockIdx.x * 64;

    for (int i = tid; i < 4096; i += 256) Bs[i] = W[i];
    for (int i = tid; i < 4096; i += 256) {
        int r = i >> 6, k = i & 63;
        int gr = row0 + r;
        At[k * 68 + r] = (gr < n) ? x[gr * 64 + k] : 0.0f;
    }
    __syncthreads();

    const int tx = tid & 15;
    const int ty = tid >> 4;
    const unsigned long long* Bs64 = (const unsigned long long*)Bs;

    unsigned long long acc[4][2];
#pragma unroll
    for (int i = 0; i < 4; i++) { acc[i][0] = 0ULL; acc[i][1] = 0ULL; }

#pragma unroll
    for (int k = 0; k < 64; k++) {
        float4 a = *(const float4*)&At[k * 68 + ty * 4];
        unsigned long long b01 = Bs64[k * 32 + tx * 2];
        unsigned long long b23 = Bs64[k * 32 + tx * 2 + 1];
        unsigned long long ax = splat2(a.x);
        unsigned long long ay = splat2(a.y);
        unsigned long long az = splat2(a.z);
        unsigned long long aw = splat2(a.w);
        ffma2(acc[0][0], ax, b01); ffma2(acc[0][1], ax, b23);
        ffma2(acc[1][0], ay, b01); ffma2(acc[1][1], ay, b23);
        ffma2(acc[2][0], az, b01); ffma2(acc[2][1], az, b23);
        ffma2(acc[3][0], aw, b01); ffma2(acc[3][1], aw, b23);
    }

#pragma unroll
    for (int i = 0; i < 4; i++) {
        int r = row0 + ty * 4 + i;
        if (r < n) {
            float2 lo = unpack2(acc[i][0]);
            float2 hi = unpack2(acc[i][1]);
            __half2 h0 = __floats2half2_rn(lo.x, lo.y);
            __half2 h1 = __floats2half2_rn(hi.x, hi.y);
            uint2 u;
            u.x = *(unsigned*)&h0;
            u.y = *(unsigned*)&h1;
            ((uint2*)g_xlh)[r * 16 + tx] = u;
        }
    }
}

// ---------------- single-kernel exclusive scan (decoupled lookback) --------
__device__ __forceinline__ int warp_incl_scan(int v) {
    int lane = threadIdx.x & 31;
#pragma unroll
    for (int o = 1; o < 32; o <<= 1) {
        int t = __shfl_up_sync(0xffffffffu, v, o);
        if (lane >= o) v += t;
    }
    return v;
}

__global__ __launch_bounds__(256) void k_scan(int n, int e) {
    __shared__ int wsum[8];
    __shared__ int s_prefix, s_total;
    const int tid = threadIdx.x;
    const int b = blockIdx.x;
    const int i = b * 256 + tid;

    int v = (i < n) ? g_deg[i] : 0;
    if (i < n) g_dinv[i] = rsqrtf((float)(v + 1));

    int inc = warp_incl_scan(v);
    int lane = tid & 31, w = tid >> 5;
    if (lane == 31) wsum[w] = inc;
    __syncthreads();
    if (w == 0) {
        int s = (lane < 8) ? wsum[lane] : 0;
        int si = warp_incl_scan(s);
        if (lane < 8) wsum[lane] = si - s;
    }
    __syncthreads();
    inc += wsum[w];
    if (tid == 255) s_total = inc;
    __syncthreads();
    int total = s_total;

    if (tid == 0) {
        unsigned long long pack =
            ((unsigned long long)(b == 0 ? 2u : 1u) << 32) | (unsigned)total;
        atomicExch(&g_status[b], pack);
    }

    if (b == 0) {
        if (tid == 0) s_prefix = 0;
    } else if (tid < 32) {
        int prefix = 0;
        int look = b - 1;
        while (true) {
            int idx = look - tid;
            unsigned long long st;
            unsigned flag;
            do {
                st = (idx >= 0) ? *((volatile unsigned long long*)&g_status[idx])
                                : (2ULL << 32);
                flag = (unsigned)(st >> 32);
            } while (__any_sync(0xffffffffu, flag == 0u));
            int val = (int)(st & 0xffffffffULL);
            unsigned ball = __ballot_sync(0xffffffffu, flag == 2u);
            if (ball) {
                int fi = __ffs(ball) - 1;
                int contrib = (tid <= fi) ? val : 0;
#pragma unroll
                for (int o = 16; o; o >>= 1)
                    contrib += __shfl_down_sync(0xffffffffu, contrib, o);
                if (tid == 0) prefix += contrib;
                break;
            } else {
                int contrib = val;
#pragma unroll
                for (int o = 16; o; o >>= 1)
                    contrib += __shfl_down_sync(0xffffffffu, contrib, o);
                if (tid == 0) prefix += contrib;
                look -= 32;
            }
        }
        if (tid == 0) s_prefix = prefix;
    }
    __syncthreads();
    int prefix = s_prefix;

    if (b != 0 && tid == 0) {
        unsigned long long pack = (2ULL << 32) | (unsigned)(prefix + total);
        atomicExch(&g_status[b], pack);
    }

    int exc = prefix + inc - v;
    if (i < n) { g_rowstart[i] = exc; g_cursor[i] = exc; }
    if (b == 0 && tid == 0) g_rowstart[n] = e;
}

// ---------------- CSR fill + xl pre-scale (+ re-zero deg) ------------------
// Thread i (< n*16) scales 4 halves of g_xlh by dinv[node] in place.
__global__ void k_fill(int n, int e) {
    int i = blockIdx.x * blockDim.x + threadIdx.x;
    if (i < n) g_deg[i] = 0;
    if (i < e) {
        int d = g_eidx[e + i];
        int pos = atomicAdd(&g_cursor[d], 1);
        g_csr_src[pos] = g_eidx[i];
    }
    if (i < n * 16) {
        float w = g_dinv[i >> 4];
        uint2* p4 = (uint2*)g_xlh + i;
        uint2 u = *p4;
        float4 f = h4_to_f4(u);
        __half2 h0 = __floats2half2_rn(f.x * w, f.y * w);
        __half2 h1 = __floats2half2_rn(f.z * w, f.w * w);
        u.x = *(unsigned*)&h0;
        u.y = *(unsigned*)&h1;
        *p4 = u;
    }
}

// ---------------- fused: layer-1 gather (fp16 rows) + relu + b1 + GEMM2 ----
// Rows are pre-scaled fp16 (128B = 1 cache line). Accumulate fp32.
__global__ __launch_bounds__(256) void k_gather1_gemm2(const float* __restrict__ b1,
                                                       const float* __restrict__ W2,
                                                       int n) {
    __shared__ float Hs[16 * 68];
    __shared__ float W2s[64 * 16];
    const int tid = threadIdx.x;

    for (int i = tid; i < 64 * 16; i += 256) {
        int k = i >> 4, j = i & 15;
        W2s[i] = (j < 10) ? W2[k * 10 + j] : 0.0f;
    }

    int t = blockIdx.x * 256 + tid;
    int nd = t >> 4;
    int c = t & 15;
    int g = tid >> 4;

    float4 hv = make_float4(0.f, 0.f, 0.f, 0.f);
    if (nd < n) {
        int beg = g_rowstart[nd], end = g_rowstart[nd + 1];
        float di = g_dinv[nd];
        const uint2* xlh = (const uint2*)g_xlh;

        float4 acc = h4_to_f4(xlh[nd * 16 + c]);   // self term (pre-scaled)

        int j = beg;
        for (; j + 3 < end; j += 4) {
            int s0 = g_csr_src[j];
            int s1 = g_csr_src[j + 1];
            int s2 = g_csr_src[j + 2];
            int s3 = g_csr_src[j + 3];
            float4 v0 = h4_to_f4(xlh[s0 * 16 + c]);
            float4 v1 = h4_to_f4(xlh[s1 * 16 + c]);
            float4 v2 = h4_to_f4(xlh[s2 * 16 + c]);
            float4 v3 = h4_to_f4(xlh[s3 * 16 + c]);
            acc.x += (v0.x + v1.x) + (v2.x + v3.x);
            acc.y += (v0.y + v1.y) + (v2.y + v3.y);
            acc.z += (v0.z + v1.z) + (v2.z + v3.z);
            acc.w += (v0.w + v1.w) + (v2.w + v3.w);
        }
        for (; j < end; ++j) {
            float4 v0 = h4_to_f4(xlh[g_csr_src[j] * 16 + c]);
            acc.x += v0.x; acc.y += v0.y; acc.z += v0.z; acc.w += v0.w;
        }
        float4 bb = *(const float4*)&b1[c * 4];
        hv.x = fmaxf(fmaf(acc.x, di, bb.x), 0.0f);
        hv.y = fmaxf(fmaf(acc.y, di, bb.y), 0.0f);
        hv.z = fmaxf(fmaf(acc.z, di, bb.z), 0.0f);
        hv.w = fmaxf(fmaf(acc.w, di, bb.w), 0.0f);
    }
    Hs[g * 68 + c * 4 + 0] = hv.x;
    Hs[g * 68 + c * 4 + 1] = hv.y;
    Hs[g * 68 + c * 4 + 2] = hv.z;
    Hs[g * 68 + c * 4 + 3] = hv.w;
    __syncthreads();

    int r = blockIdx.x * 16 + g;
    if (r >= n) return;
    int j = tid & 15;
    float accl = 0.0f;
#pragma unroll
    for (int k = 0; k < 64; k++) accl = fmaf(Hs[g * 68 + k], W2s[k * 16 + j], accl);
    g_l[r * 16 + j] = accl * g_dinv[r];   // pre-scale for gather2
}

// ---------------- layer-2 gather + b2 + log_softmax (fused) ----------------
__global__ __launch_bounds__(256) void k_gather2_softmax(const float* __restrict__ b2,
                                                         float* __restrict__ out,
                                                         int n) {
    int t = blockIdx.x * 256 + threadIdx.x;
    int nd = t >> 4;
    if (nd >= n) return;
    int c = t & 15;

    int beg = g_rowstart[nd], end = g_rowstart[nd + 1];
    float di = g_dinv[nd];
    float acc = g_l[nd * 16 + c];   // self term (already dinv-scaled)

    int j = beg;
    for (; j + 3 < end; j += 4) {
        int s0 = g_csr_src[j];
        int s1 = g_csr_src[j + 1];
        int s2 = g_csr_src[j + 2];
        int s3 = g_csr_src[j + 3];
        float v0 = g_l[s0 * 16 + c];
        float v1 = g_l[s1 * 16 + c];
        float v2 = g_l[s2 * 16 + c];
        float v3 = g_l[s3 * 16 + c];
        acc += (v0 + v1) + (v2 + v3);
    }
    for (; j < end; ++j) acc += g_l[g_csr_src[j] * 16 + c];
    acc *= di;

    float v = (c < 10) ? acc + b2[c] : -1e30f;
    float m = v;
#pragma unroll
    for (int o = 8; o > 0; o >>= 1) m = fmaxf(m, __shfl_xor_sync(0xffffffffu, m, o, 16));
    float ex = (c < 10) ? __expf(v - m) : 0.0f;
    float ssum = ex;
#pragma unroll
    for (int o = 8; o > 0; o >>= 1) ssum += __shfl_xor_sync(0xffffffffu, ssum, o, 16);
    float lse = m + __logf(ssum);
    if (c < 10) out[nd * 10 + c] = v - lse;
}

// ---------------- launcher --------------------------------------------------
extern "C" void kernel_launch(void* const* d_in, const int* in_sizes, int n_in,
                              void* d_out, int out_size) {
    const float* x   = (const float*)d_in[0];
    const void*  ei  = d_in[1];               // [2, E], int32 or int64 (detected)
    const float* W1  = (const float*)d_in[2];
    const float* b1  = (const float*)d_in[3];
    const float* W2  = (const float*)d_in[4];
    const float* b2  = (const float*)d_in[5];
    float*       out = (float*)d_out;

    const int n  = in_sizes[0] / 64;   // 50000
    const int e2 = in_sizes[1];        // 2*E elements
    const int e  = e2 / 2;             // 800000
    const int nb = (n + 255) / 256;    // 196 scan blocks (<=256 statuses)

    const int gemm_blocks = (n + 63) / 64;       // 782
    const int conv_blocks = (e2 + 255) / 256;    // 6250
    const long long fill_threads = (long long)e > (long long)n * 16 ? e : (long long)n * 16;

    k_gemm1_convert  <<<gemm_blocks + conv_blocks, 256>>>(x, W1, ei, n, e2, gemm_blocks);
    k_scan           <<<nb, 256>>>(n, e);
    k_fill           <<<(int)((fill_threads + 255) / 256), 256>>>(n, e);
    k_gather1_gemm2  <<<(n * 16 + 255) / 256, 256>>>(b1, W2, n);
    k_gather2_softmax<<<(n * 16 + 255) / 256, 256>>>(b2, out, n);
}